// round 10
// baseline (speedup 1.0000x reference)
#include <cuda_runtime.h>
#include <cuda_fp16.h>
#include <math.h>

#define S     8192
#define SMASK 8191
#define HS    4096      // S/2
#define W     64
#define MODES 256
#define RTOT  4096      // 64 batches * 64 channels
#define KA    640       // inv-GEMM A width: (128re+128im+64pw) even + same odd
#define INV_SCALE 0.000244140625f   // 1/4096

// ---------------- scratch (device globals; no allocations) ----------------
__device__ __half d_E0h[RTOT * HS], d_E0l[RTOT * HS];
__device__ __half d_O0h[RTOT * HS], d_O0l[RTOT * HS];
__device__ __half d_E1h[RTOT * HS], d_E1l[RTOT * HS];
__device__ __half d_O1h[RTOT * HS], d_O1l[RTOT * HS];
__device__ __half d_Bf0h[HS * 256], d_Bf0l[HS * 256];   // fwd basis even modes [n][c]
__device__ __half d_Bf1h[HS * 256], d_Bf1l[HS * 256];   // fwd basis odd  modes [n][c]
__device__ __half d_BiSh[256 * HS], d_BiSl[256 * HS];   // inv basis even [c][n]
__device__ __half d_BiDh[256 * HS], d_BiDl[256 * HS];   // inv basis odd  [c][n]
__device__ float  d_CT[512 * RTOT];                     // fwd out, [c][r]
__device__ __half d_Ah[RTOT * KA], d_Al[RTOT * KA];     // inv-GEMM A
__device__ float  d_WTr[4 * 256 * 64 * 64];             // spectral W re [l][k][i][o]
__device__ float  d_WTi[4 * 256 * 64 * 64];             // spectral W im
__device__ float  d_tab[8192];                          // cos table

__device__ __forceinline__ float gelu_f(float x) {
    return 0.5f * x * (1.0f + erff(x * 0.7071067811865476f));
}

// ---------------- PTX helpers ----------------------------------------------
#define CP_ASYNC(dst, src) \
    asm volatile("cp.async.cg.shared.global [%0], [%1], 16;" :: "r"(dst), "l"(src))
#define CP_COMMIT() asm volatile("cp.async.commit_group;")
#define CP_WAIT1()  asm volatile("cp.async.wait_group 1;")

__device__ __forceinline__ void ldsm4(unsigned a, unsigned* r) {
    asm volatile("ldmatrix.sync.aligned.m8n8.x4.shared.b16 {%0,%1,%2,%3}, [%4];"
                 : "=r"(r[0]), "=r"(r[1]), "=r"(r[2]), "=r"(r[3]) : "r"(a));
}
__device__ __forceinline__ void ldsm4t(unsigned a, unsigned* r) {
    asm volatile("ldmatrix.sync.aligned.m8n8.x4.trans.shared.b16 {%0,%1,%2,%3}, [%4];"
                 : "=r"(r[0]), "=r"(r[1]), "=r"(r[2]), "=r"(r[3]) : "r"(a));
}
__device__ __forceinline__ void mma16816(float* c, const unsigned* a, const unsigned* b) {
    asm volatile("mma.sync.aligned.m16n8k16.row.col.f32.f16.f16.f32 "
                 "{%0,%1,%2,%3}, {%4,%5,%6,%7}, {%8,%9}, {%0,%1,%2,%3};"
                 : "+f"(c[0]), "+f"(c[1]), "+f"(c[2]), "+f"(c[3])
                 : "r"(a[0]), "r"(a[1]), "r"(a[2]), "r"(a[3]), "r"(b[0]), "r"(b[1]));
}
__device__ __forceinline__ void split_store(float v, __half* ph, __half* pl) {
    __half h = __float2half_rn(v);
    *ph = h;
    *pl = __float2half_rn(v - __half2float(h));
}

// ---------------- basis via cos table ---------------------------------------
__global__ void gen_table() {
    int j = blockIdx.x * 256 + threadIdx.x;
    d_tab[j] = cospif((float)j * (1.0f / 4096.0f));
}
__global__ void gen_basis() {
    int idx = blockIdx.x * 256 + threadIdx.x;   // n*256 + c
    int n = idx >> 8, c = idx & 255, m = c & 127;
    bool sp = (c >= 128);
    #pragma unroll
    for (int par = 0; par < 2; par++) {
        int k = 2 * m + par;
        int j = (k * n) & SMASK;
        float v = sp ? d_tab[(j + 2048) & SMASK] : d_tab[j];   // -sin / cos
        __half h = __float2half_rn(v);
        __half l = __float2half_rn(v - __half2float(h));
        if (par == 0) {
            d_Bf0h[n * 256 + c] = h; d_Bf0l[n * 256 + c] = l;
            d_BiSh[c * HS + n]  = h; d_BiSl[c * HS + n]  = l;
        } else {
            d_Bf1h[n * 256 + c] = h; d_Bf1l[n * 256 + c] = l;
            d_BiDh[c * HS + n]  = h; d_BiDl[c * HS + n]  = l;
        }
    }
}

// ---------------- spectral-weight transpose: [l,i,o,k] -> [l,k,i,o] --------
__global__ void wtrans(const float* __restrict__ swr, const float* __restrict__ swi) {
    __shared__ float t[32][33];
    const float* src = blockIdx.z ? swi : swr;
    float*       dst = blockIdx.z ? d_WTi : d_WTr;
    int k0 = blockIdx.x * 32, R0 = blockIdx.y * 32;
    t[threadIdx.y][threadIdx.x] = src[(R0 + threadIdx.y) * 256 + k0 + threadIdx.x];
    __syncthreads();
    int l = R0 >> 12, io0 = R0 & 4095;
    dst[(l * 256 + k0 + threadIdx.y) * 4096 + io0 + threadIdx.x] = t[threadIdx.x][threadIdx.y];
}

// ---------------- lifting + fold (2 elems/thread, half2 stores) -------------
__global__ void lift_fold(const float* __restrict__ u, const float* __restrict__ fc0w,
                          const float* __restrict__ fc0b,
                          __half* __restrict__ Eh, __half* __restrict__ El,
                          __half* __restrict__ Oh, __half* __restrict__ Ol) {
    int idx = blockIdx.x * 256 + threadIdx.x;   // (b*64+w)*2048 + n/2
    int n = (idx & 2047) * 2;
    int r = idx >> 11;
    int w = r & 63;
    int b = r >> 6;
    float w0 = fc0w[w], w1 = fc0w[64 + w], bb = fc0b[w];
    float2 ua = *(const float2*)&u[(size_t)b * S + n];
    float2 ub = *(const float2*)&u[(size_t)b * S + n + HS];
    const float gi = 1.0f / 8191.0f;
    float lo0 = ua.x * w0 + (float)n * gi * w1 + bb;
    float lo1 = ua.y * w0 + (float)(n + 1) * gi * w1 + bb;
    float hi0 = ub.x * w0 + (float)(n + HS) * gi * w1 + bb;
    float hi1 = ub.y * w0 + (float)(n + HS + 1) * gi * w1 + bb;
    float E0 = lo0 + hi0, E1 = lo1 + hi1;
    float O0 = lo0 - hi0, O1 = lo1 - hi1;
    size_t off = (size_t)r * HS + n;
    __half eh0 = __float2half_rn(E0), eh1 = __float2half_rn(E1);
    __half oh0 = __float2half_rn(O0), oh1 = __float2half_rn(O1);
    *(__half2*)(Eh + off) = __halves2half2(eh0, eh1);
    *(__half2*)(El + off) = __halves2half2(__float2half_rn(E0 - __half2float(eh0)),
                                           __float2half_rn(E1 - __half2float(eh1)));
    *(__half2*)(Oh + off) = __halves2half2(oh0, oh1);
    *(__half2*)(Ol + off) = __halves2half2(__float2half_rn(O0 - __half2float(oh0)),
                                           __float2half_rn(O1 - __half2float(oh1)));
}

// ---------------- forward DFT: tensor-core GEMM ----------------------------
// CTA 128(m) x 64(n), 8 warps, warp tile 32x32, 2 CTAs/SM. No split-K.
// z=0: even modes from E; z=1: odd modes from O.
__global__ __launch_bounds__(256, 2) void tc_fwd(const __half* __restrict__ Eh,
                                                 const __half* __restrict__ El,
                                                 const __half* __restrict__ Oh,
                                                 const __half* __restrict__ Ol) {
    extern __shared__ __align__(16) char smem[];
    unsigned sbase = (unsigned)__cvta_generic_to_shared(smem);
    const int tid = threadIdx.x, lane = tid & 31, warp = tid >> 5;
    const int bm = blockIdx.y, bn = blockIdx.x, z = blockIdx.z;
    const __half* gAh = (z ? Oh : Eh) + (size_t)bm * 128 * HS;
    const __half* gAl = (z ? Ol : El) + (size_t)bm * 128 * HS;
    const __half* gBh = (z ? d_Bf1h : d_Bf0h) + bn * 64;
    const __half* gBl = (z ? d_Bf1l : d_Bf0l) + bn * 64;

    // stage (24KB): Ah 0..8191, Al 8192..16383, Bh 16384..20479, Bl 20480..24575
    auto issue = [&](int st, int k0) {
        unsigned s0 = sbase + (unsigned)st * 24576u;
        #pragma unroll
        for (int j = 0; j < 2; j++) {
            int id = tid * 2 + j;                   // 0..511
            int r = id >> 2, c = id & 3;            // A: 128 rows x 4 chunks
            unsigned sa = s0 + r * 64 + ((c ^ ((r >> 1) & 3)) << 4);
            size_t ga = (size_t)r * HS + k0 + c * 8;
            CP_ASYNC(sa, gAh + ga);
            CP_ASYNC(sa + 8192u, gAl + ga);
        }
        {   int k = tid >> 3, cc = tid & 7;         // B: 32 rows x 8 chunks (64 cols)
            unsigned sb = s0 + 16384u + k * 128 + ((cc ^ (k & 7)) << 4);
            size_t gb = (size_t)(k0 + k) * 256 + cc * 8;
            CP_ASYNC(sb, gBh + gb);
            CP_ASYNC(sb + 4096u, gBl + gb);
        }
        CP_COMMIT();
    };

    float C[2][4][4];
    #pragma unroll
    for (int i = 0; i < 2; i++)
        #pragma unroll
        for (int j = 0; j < 4; j++)
            #pragma unroll
            for (int q = 0; q < 4; q++) C[i][j][q] = 0.0f;

    const int m0w = (warp >> 1) * 32, n0w = (warp & 1) * 32;

    issue(0, 0); issue(1, 32);
    for (int i = 0; i < 128; i++) {
        CP_WAIT1();
        __syncthreads();
        if (i + 2 < 128) issue((i + 2) % 3, (i + 2) * 32);
        unsigned s0 = sbase + (unsigned)(i % 3) * 24576u;
        #pragma unroll
        for (int ks = 0; ks < 2; ks++) {
            const int kk = ks * 16;
            unsigned ah[2][4], al[2][4];
            #pragma unroll
            for (int mi = 0; mi < 2; mi++) {
                int r = m0w + mi * 16 + (lane & 15);
                int ch = (kk >> 3) + (lane >> 4);
                unsigned ad = s0 + r * 64 + ((ch ^ ((r >> 1) & 3)) << 4);
                ldsm4(ad, ah[mi]);
                ldsm4(ad + 8192u, al[mi]);
            }
            unsigned bh[4][2], bl[4][2];
            #pragma unroll
            for (int g = 0; g < 2; g++) {
                int kr = kk + (lane & 7) + ((lane >> 3) & 1) * 8;
                int ch = ((n0w + g * 16) >> 3) + (lane >> 4);
                unsigned ad = s0 + 16384u + kr * 128 + ((ch ^ (kr & 7)) << 4);
                unsigned t[4];
                ldsm4t(ad, t);
                bh[2*g][0] = t[0]; bh[2*g][1] = t[1]; bh[2*g+1][0] = t[2]; bh[2*g+1][1] = t[3];
                ldsm4t(ad + 4096u, t);
                bl[2*g][0] = t[0]; bl[2*g][1] = t[1]; bl[2*g+1][0] = t[2]; bl[2*g+1][1] = t[3];
            }
            #pragma unroll
            for (int mi = 0; mi < 2; mi++)
                #pragma unroll
                for (int nj = 0; nj < 4; nj++) {
                    mma16816(C[mi][nj], ah[mi], bh[nj]);
                    mma16816(C[mi][nj], ah[mi], bl[nj]);
                    mma16816(C[mi][nj], al[mi], bh[nj]);
                }
        }
    }
    // store into d_CT with mode remap: local col cl -> mode k=2*cl+z (Re) / Im block
    const int r0 = bm * 128 + m0w + (lane >> 2);
    const int cl0 = bn * 64 + n0w + (lane & 3) * 2;
    #pragma unroll
    for (int mi = 0; mi < 2; mi++)
        #pragma unroll
        for (int nj = 0; nj < 4; nj++) {
            int r = r0 + mi * 16;
            int cl = cl0 + nj * 8;
            int row0 = (cl < 128) ? (2 * cl + z) : (256 + 2 * (cl - 128) + z);
            d_CT[(size_t)row0 * RTOT + r]           = C[mi][nj][0];
            d_CT[(size_t)(row0 + 2) * RTOT + r]     = C[mi][nj][1];
            d_CT[(size_t)row0 * RTOT + r + 8]       = C[mi][nj][2];
            d_CT[(size_t)(row0 + 2) * RTOT + r + 8] = C[mi][nj][3];
        }
}

// ---------------- per-mode complex channel mix -> inv-GEMM A ----------------
__global__ __launch_bounds__(256) void mixk(int l) {
    extern __shared__ float sm[];
    float* Wr = sm;        float* Wi = sm + 4096;
    float* Xr = sm + 8192; float* Xi = sm + 12288;
    int k = blockIdx.x, tid = threadIdx.x;
    const float* wr = d_WTr + (size_t)(l * MODES + k) * 4096;
    const float* wi = d_WTi + (size_t)(l * MODES + k) * 4096;
    const float* cr = d_CT + (size_t)k * RTOT;
    const float* ci = d_CT + (size_t)(MODES + k) * RTOT;
    #pragma unroll
    for (int j = 0; j < 16; j++) {
        int idx = tid + 256 * j;
        Wr[idx] = wr[idx]; Wi[idx] = wi[idx];
        Xr[idx] = cr[idx]; Xi[idx] = ci[idx];
    }
    __syncthreads();
    int o = tid & 63;
    int b0 = tid >> 6;
    float ar[16], ai[16];
    #pragma unroll
    for (int j = 0; j < 16; j++) { ar[j] = 0.0f; ai[j] = 0.0f; }
    for (int i = 0; i < 64; i++) {
        float wre = Wr[i * 64 + o], wim = Wi[i * 64 + o];
        #pragma unroll
        for (int j = 0; j < 16; j++) {
            int b = b0 + 4 * j;
            float xr = Xr[b * 64 + i], xi = Xi[b * 64 + i];
            ar[j] += xr * wre - xi * wim;
            ai[j] += xr * wim + xi * wre;
        }
    }
    int par = k & 1, m = k >> 1;
    float fa = (k == 0) ? 0.5f : 1.0f;
    #pragma unroll
    for (int j = 0; j < 16; j++) {
        int lin = tid + 256 * j;                 // = b*64 + o
        size_t base = (size_t)lin * KA + par * 320;
        split_store(ar[j] * fa, &d_Ah[base + m], &d_Al[base + m]);
        split_store((k == 0) ? 0.0f : ai[j], &d_Ah[base + 128 + m], &d_Al[base + 128 + m]);
    }
}

// ---------------- pack pointwise weights into inv-GEMM A --------------------
__global__ void pwpack(const float* __restrict__ pw) {
    int idx = blockIdx.x * 256 + threadIdx.x;    // b*4096 + o*64 + i
    int i = idx & 63, o = (idx >> 6) & 63, b = idx >> 12;
    float v = pw[o * 64 + i] * 2048.0f;
    size_t base = (size_t)(b * 64 + o) * KA;
    split_store(v, &d_Ah[base + 256 + i], &d_Al[base + 256 + i]);
    split_store(v, &d_Ah[base + 576 + i], &d_Al[base + 576 + i]);
}

// ---------------- fused inverse DFT + pointwise + gelu + refold -------------
// Per (b, n-tile): acc_s = A_sum @ [BiS ; E_b], acc_d = A_dif @ [BiD ; O_b]
// y_lo = (s+d)/4096 + bias, y_hi = (s-d)/4096 + bias; emit E'=g(lo)+g(hi), O'=g(lo)-g(hi)
#define MMABLK(Cx) \
    _Pragma("unroll") \
    for (int mi = 0; mi < 2; mi++) \
        _Pragma("unroll") \
        for (int nj = 0; nj < 4; nj++) { \
            mma16816(Cx[mi][nj], ah[mi], bh[nj]); \
            mma16816(Cx[mi][nj], ah[mi], bl[nj]); \
            mma16816(Cx[mi][nj], al[mi], bh[nj]); \
        }

__global__ __launch_bounds__(256, 2) void tc_inv(const __half* __restrict__ Einh,
                                                 const __half* __restrict__ Einl,
                                                 const __half* __restrict__ Oinh,
                                                 const __half* __restrict__ Oinl,
                                                 __half* __restrict__ Eoh,
                                                 __half* __restrict__ Eol,
                                                 __half* __restrict__ Ooh,
                                                 __half* __restrict__ Ool,
                                                 const float* __restrict__ pwb,
                                                 int dogelu) {
    extern __shared__ __align__(16) char smem[];
    unsigned sbase = (unsigned)__cvta_generic_to_shared(smem);
    const int tid = threadIdx.x, lane = tid & 31, warp = tid >> 5;
    const int b = blockIdx.y;
    const int n0 = blockIdx.x * 128;
    const size_t bofs = (size_t)b * 64 * HS;
    const __half* gAh = d_Ah + (size_t)b * 64 * KA;
    const __half* gAl = d_Al + (size_t)b * 64 * KA;

    // stage (24KB): Ah 0..4095, Al 4096..8191, Bh 8192..16383, Bl 16384..24575
    auto issue = [&](int st, int c0) {
        unsigned s0 = sbase + (unsigned)st * 24576u;
        {   int r = tid >> 2, c = tid & 3;          // A: 64 rows x 4 chunks
            unsigned sa = s0 + r * 64 + ((c ^ ((r >> 1) & 3)) << 4);
            size_t ga = (size_t)r * KA + c0 + c * 8;
            CP_ASYNC(sa, gAh + ga);
            CP_ASYNC(sa + 4096u, gAl + ga);
        }
        #pragma unroll
        for (int j = 0; j < 2; j++) {
            int id = tid * 2 + j;
            int k = id >> 4, cc = id & 15;          // B: 32 rows x 16 chunks
            int cg = c0 + k;
            const __half *ph, *pl;
            if (cg < 256)      { size_t o = (size_t)cg * HS + n0 + cc * 8;          ph = d_BiSh + o;       pl = d_BiSl + o; }
            else if (cg < 320) { size_t o = (size_t)(cg - 256) * HS + n0 + cc * 8;  ph = Einh + bofs + o;  pl = Einl + bofs + o; }
            else if (cg < 576) { size_t o = (size_t)(cg - 320) * HS + n0 + cc * 8;  ph = d_BiDh + o;       pl = d_BiDl + o; }
            else               { size_t o = (size_t)(cg - 576) * HS + n0 + cc * 8;  ph = Oinh + bofs + o;  pl = Oinl + bofs + o; }
            unsigned sb = s0 + 8192u + k * 256 + ((cc ^ (k & 7)) << 4);
            CP_ASYNC(sb, ph);
            CP_ASYNC(sb + 8192u, pl);
        }
        CP_COMMIT();
    };

    float Cs[2][4][4], Cd[2][4][4];
    #pragma unroll
    for (int i = 0; i < 2; i++)
        #pragma unroll
        for (int j = 0; j < 4; j++)
            #pragma unroll
            for (int q = 0; q < 4; q++) { Cs[i][j][q] = 0.0f; Cd[i][j][q] = 0.0f; }

    const int m0w = (warp >> 2) * 32, n0w = (warp & 3) * 32;

    issue(0, 0); issue(1, 32);
    for (int i = 0; i < 20; i++) {
        CP_WAIT1();
        __syncthreads();
        if (i + 2 < 20) issue((i + 2) % 3, (i + 2) * 32);
        unsigned s0 = sbase + (unsigned)(i % 3) * 24576u;
        #pragma unroll
        for (int ks = 0; ks < 2; ks++) {
            const int kk = ks * 16;
            unsigned ah[2][4], al[2][4];
            #pragma unroll
            for (int mi = 0; mi < 2; mi++) {
                int r = m0w + mi * 16 + (lane & 15);
                int ch = (kk >> 3) + (lane >> 4);
                unsigned ad = s0 + r * 64 + ((ch ^ ((r >> 1) & 3)) << 4);
                ldsm4(ad, ah[mi]);
                ldsm4(ad + 4096u, al[mi]);
            }
            unsigned bh[4][2], bl[4][2];
            #pragma unroll
            for (int g = 0; g < 2; g++) {
                int kr = kk + (lane & 7) + ((lane >> 3) & 1) * 8;
                int ch = ((n0w + g * 16) >> 3) + (lane >> 4);
                unsigned ad = s0 + 8192u + kr * 256 + ((ch ^ (kr & 7)) << 4);
                unsigned t[4];
                ldsm4t(ad, t);
                bh[2*g][0] = t[0]; bh[2*g][1] = t[1]; bh[2*g+1][0] = t[2]; bh[2*g+1][1] = t[3];
                ldsm4t(ad + 8192u, t);
                bl[2*g][0] = t[0]; bl[2*g][1] = t[1]; bl[2*g+1][0] = t[2]; bl[2*g+1][1] = t[3];
            }
            if (i < 10) { MMABLK(Cs) } else { MMABLK(Cd) }
        }
    }
    // epilogue
    const int o0 = m0w + (lane >> 2);
    const int nl0 = n0w + (lane & 3) * 2;
    #pragma unroll
    for (int mi = 0; mi < 2; mi++)
        #pragma unroll
        for (int h = 0; h < 2; h++) {
            int o = o0 + mi * 16 + h * 8;
            float bias = pwb[o];
            size_t rowo = ((size_t)(b * 64 + o)) * HS;
            #pragma unroll
            for (int nj = 0; nj < 4; nj++) {
                int ng = n0 + nl0 + nj * 8;
                float s0v = Cs[mi][nj][h * 2],     d0v = Cd[mi][nj][h * 2];
                float s1v = Cs[mi][nj][h * 2 + 1], d1v = Cd[mi][nj][h * 2 + 1];
                float ylo0 = (s0v + d0v) * INV_SCALE + bias;
                float yhi0 = (s0v - d0v) * INV_SCALE + bias;
                float ylo1 = (s1v + d1v) * INV_SCALE + bias;
                float yhi1 = (s1v - d1v) * INV_SCALE + bias;
                if (dogelu) {
                    ylo0 = gelu_f(ylo0); yhi0 = gelu_f(yhi0);
                    ylo1 = gelu_f(ylo1); yhi1 = gelu_f(yhi1);
                }
                float E0 = ylo0 + yhi0, O0 = ylo0 - yhi0;
                float E1 = ylo1 + yhi1, O1 = ylo1 - yhi1;
                __half eh0 = __float2half_rn(E0), eh1 = __float2half_rn(E1);
                __half el0 = __float2half_rn(E0 - __half2float(eh0));
                __half el1 = __float2half_rn(E1 - __half2float(eh1));
                __half oh0 = __float2half_rn(O0), oh1 = __float2half_rn(O1);
                __half ol0 = __float2half_rn(O0 - __half2float(oh0));
                __half ol1 = __float2half_rn(O1 - __half2float(oh1));
                *(__half2*)(Eoh + rowo + ng) = __halves2half2(eh0, eh1);
                *(__half2*)(Eol + rowo + ng) = __halves2half2(el0, el1);
                *(__half2*)(Ooh + rowo + ng) = __halves2half2(oh0, oh1);
                *(__half2*)(Ool + rowo + ng) = __halves2half2(ol0, ol1);
            }
        }
}

// ---------------- head: gelu(x^T @ fc1 + b1) @ fc2 + b2 --------------------
__global__ __launch_bounds__(256) void headk(const __half* __restrict__ Eh,
                                             const __half* __restrict__ El,
                                             const __half* __restrict__ Oh,
                                             const __half* __restrict__ Ol,
                                             const float* __restrict__ fc1w,
                                             const float* __restrict__ fc1b,
                                             const float* __restrict__ fc2w,
                                             const float* __restrict__ fc2b,
                                             float* __restrict__ out) {
    extern __shared__ float sm[];
    float* fc1s = sm;            // [64][128]
    float* xs   = sm + 8192;     // [64][128], reused for reduction
    float* b1s  = sm + 16384;    // [128]
    float* fc2s = sm + 16512;    // [128]
    int b = blockIdx.y;
    int s0 = blockIdx.x * 128;
    int tid = threadIdx.x;
    int hi = (s0 >= HS);
    int sh = s0 & (HS - 1);
    #pragma unroll
    for (int j = 0; j < 32; j++) {
        int idx = tid + 256 * j;
        fc1s[idx] = fc1w[idx];
        size_t off = (size_t)(b * 64 + (idx >> 7)) * HS + sh + (idx & 127);
        float e = __half2float(Eh[off]) + __half2float(El[off]);
        float o = __half2float(Oh[off]) + __half2float(Ol[off]);
        xs[idx] = 0.5f * (hi ? (e - o) : (e + o));
    }
    if (tid < 128) { b1s[tid] = fc1b[tid]; fc2s[tid] = fc2w[tid]; }
    __syncthreads();

    int tm = tid >> 4, tn = tid & 15;
    float acc[8][8];
    #pragma unroll
    for (int i = 0; i < 8; i++)
        #pragma unroll
        for (int j = 0; j < 8; j++) acc[i][j] = 0.0f;
    for (int i = 0; i < 64; i++) {
        float av[8], bv[8];
        #pragma unroll
        for (int ii = 0; ii < 8; ii++) av[ii] = xs[i * 128 + tm * 8 + ii];
        #pragma unroll
        for (int jj = 0; jj < 8; jj++) bv[jj] = fc1s[i * 128 + tn * 8 + jj];
        #pragma unroll
        for (int ii = 0; ii < 8; ii++)
            #pragma unroll
            for (int jj = 0; jj < 8; jj++) acc[ii][jj] += av[ii] * bv[jj];
    }
    float part[8];
    #pragma unroll
    for (int ii = 0; ii < 8; ii++) {
        float p = 0.0f;
        #pragma unroll
        for (int jj = 0; jj < 8; jj++) {
            float h = gelu_f(acc[ii][jj] + b1s[tn * 8 + jj]);
            p += h * fc2s[tn * 8 + jj];
        }
        part[ii] = p;
    }
    __syncthreads();
    float* red = xs;
    #pragma unroll
    for (int ii = 0; ii < 8; ii++) red[(tm * 8 + ii) * 16 + tn] = part[ii];
    __syncthreads();
    if (tid < 128) {
        float ssum = fc2b[0];
        #pragma unroll
        for (int t = 0; t < 16; t++) ssum += red[tid * 16 + t];
        out[(size_t)b * S + s0 + tid] = ssum;
    }
}

// ---------------------------------------------------------------------------
extern "C" void kernel_launch(void* const* d_in, const int* in_sizes, int n_in,
                              void* d_out, int out_size) {
    const float* u    = (const float*)d_in[0];
    const float* fc0w = (const float*)d_in[1];
    const float* fc0b = (const float*)d_in[2];
    const float* swr  = (const float*)d_in[3];
    const float* swi  = (const float*)d_in[4];
    const float* pww  = (const float*)d_in[5];
    const float* pwb  = (const float*)d_in[6];
    const float* fc1w = (const float*)d_in[7];
    const float* fc1b = (const float*)d_in[8];
    const float* fc2w = (const float*)d_in[9];
    const float* fc2b = (const float*)d_in[10];
    float* out = (float*)d_out;

    cudaFuncSetAttribute(mixk,   cudaFuncAttributeMaxDynamicSharedMemorySize, 65536);
    cudaFuncSetAttribute(headk,  cudaFuncAttributeMaxDynamicSharedMemorySize, 66560);
    cudaFuncSetAttribute(tc_fwd, cudaFuncAttributeMaxDynamicSharedMemorySize, 73728);
    cudaFuncSetAttribute(tc_inv, cudaFuncAttributeMaxDynamicSharedMemorySize, 73728);

    __half *pE0h, *pE0l, *pO0h, *pO0l, *pE1h, *pE1l, *pO1h, *pO1l;
    cudaGetSymbolAddress((void**)&pE0h, d_E0h);
    cudaGetSymbolAddress((void**)&pE0l, d_E0l);
    cudaGetSymbolAddress((void**)&pO0h, d_O0h);
    cudaGetSymbolAddress((void**)&pO0l, d_O0l);
    cudaGetSymbolAddress((void**)&pE1h, d_E1h);
    cudaGetSymbolAddress((void**)&pE1l, d_E1l);
    cudaGetSymbolAddress((void**)&pO1h, d_O1h);
    cudaGetSymbolAddress((void**)&pO1l, d_O1l);

    gen_table<<<32, 256>>>();
    gen_basis<<<4096, 256>>>();
    wtrans<<<dim3(8, 512, 2), dim3(32, 32)>>>(swr, swi);
    lift_fold<<<32768, 256>>>(u, fc0w, fc0b, pE0h, pE0l, pO0h, pO0l);

    __half *Eih = pE0h, *Eil = pE0l, *Oih = pO0h, *Oil = pO0l;
    __half *Eoh = pE1h, *Eol = pE1l, *Ooh = pO1h, *Ool = pO1l;
    for (int l = 0; l < 4; l++) {
        tc_fwd<<<dim3(4, 32, 2), 256, 73728>>>(Eih, Eil, Oih, Oil);
        mixk<<<256, 256, 65536>>>(l);
        pwpack<<<1024, 256>>>(pww + l * W * W);
        tc_inv<<<dim3(32, 64), 256, 73728>>>(Eih, Eil, Oih, Oil,
                                             Eoh, Eol, Ooh, Ool,
                                             pwb + l * W, (l < 3) ? 1 : 0);
        __half* t;
        t = Eih; Eih = Eoh; Eoh = t;
        t = Eil; Eil = Eol; Eol = t;
        t = Oih; Oih = Ooh; Ooh = t;
        t = Oil; Oil = Ool; Ool = t;
    }
    headk<<<dim3(64, 64), 256, 66560>>>(Eih, Eil, Oih, Oil,
                                        fc1w, fc1b, fc2w, fc2b, out);
}

// round 12
// speedup vs baseline: 1.1198x; 1.1198x over previous
#include <cuda_runtime.h>
#include <cuda_fp16.h>
#include <math.h>

#define S     8192
#define SMASK 8191
#define HS    4096      // S/2
#define W     64
#define MODES 256
#define RTOT  4096      // 64 batches * 64 channels
#define KA    640       // inv-GEMM A width: (128re+128im+64pw) even + same odd
#define INV_SCALE 0.000244140625f   // 1/4096

// ---------------- scratch (device globals; no allocations) ----------------
__device__ __half d_E0h[RTOT * HS], d_E0l[RTOT * HS];
__device__ __half d_O0h[RTOT * HS], d_O0l[RTOT * HS];
__device__ __half d_E1h[RTOT * HS], d_E1l[RTOT * HS];
__device__ __half d_O1h[RTOT * HS], d_O1l[RTOT * HS];
__device__ __half d_Bf0h[HS * 256], d_Bf0l[HS * 256];   // fwd basis even modes [n][c]
__device__ __half d_Bf1h[HS * 256], d_Bf1l[HS * 256];   // fwd basis odd  modes [n][c]
__device__ __half d_BiSh[256 * HS], d_BiSl[256 * HS];   // inv basis even [c][n]
__device__ __half d_BiDh[256 * HS], d_BiDl[256 * HS];   // inv basis odd  [c][n]
__device__ float  d_CT[512 * RTOT];                     // fwd out, [c][r]
__device__ __half d_Ah[RTOT * KA], d_Al[RTOT * KA];     // inv-GEMM A
__device__ float  d_WTr[4 * 256 * 64 * 64];             // spectral W re [l][k][i][o]
__device__ float  d_WTi[4 * 256 * 64 * 64];             // spectral W im
__device__ float  d_tab[8192];                          // cos table

__device__ __forceinline__ float gelu_f(float x) {
    return 0.5f * x * (1.0f + erff(x * 0.7071067811865476f));
}

// ---------------- PTX helpers ----------------------------------------------
#define CP_ASYNC(dst, src) \
    asm volatile("cp.async.cg.shared.global [%0], [%1], 16;" :: "r"(dst), "l"(src))
#define CP_COMMIT() asm volatile("cp.async.commit_group;")
#define CP_WAIT1()  asm volatile("cp.async.wait_group 1;")

__device__ __forceinline__ void ldsm4(unsigned a, unsigned* r) {
    asm volatile("ldmatrix.sync.aligned.m8n8.x4.shared.b16 {%0,%1,%2,%3}, [%4];"
                 : "=r"(r[0]), "=r"(r[1]), "=r"(r[2]), "=r"(r[3]) : "r"(a));
}
__device__ __forceinline__ void ldsm4t(unsigned a, unsigned* r) {
    asm volatile("ldmatrix.sync.aligned.m8n8.x4.trans.shared.b16 {%0,%1,%2,%3}, [%4];"
                 : "=r"(r[0]), "=r"(r[1]), "=r"(r[2]), "=r"(r[3]) : "r"(a));
}
__device__ __forceinline__ void mma16816(float* c, const unsigned* a, const unsigned* b) {
    asm volatile("mma.sync.aligned.m16n8k16.row.col.f32.f16.f16.f32 "
                 "{%0,%1,%2,%3}, {%4,%5,%6,%7}, {%8,%9}, {%0,%1,%2,%3};"
                 : "+f"(c[0]), "+f"(c[1]), "+f"(c[2]), "+f"(c[3])
                 : "r"(a[0]), "r"(a[1]), "r"(a[2]), "r"(a[3]), "r"(b[0]), "r"(b[1]));
}
__device__ __forceinline__ void split_store(float v, __half* ph, __half* pl) {
    __half h = __float2half_rn(v);
    *ph = h;
    *pl = __float2half_rn(v - __half2float(h));
}

// ---------------- basis via cos table ---------------------------------------
__global__ void gen_table() {
    int j = blockIdx.x * 256 + threadIdx.x;
    d_tab[j] = cospif((float)j * (1.0f / 4096.0f));
}
__global__ void gen_basis() {
    int idx = blockIdx.x * 256 + threadIdx.x;   // n*256 + c
    int n = idx >> 8, c = idx & 255, m = c & 127;
    bool sp = (c >= 128);
    #pragma unroll
    for (int par = 0; par < 2; par++) {
        int k = 2 * m + par;
        int j = (k * n) & SMASK;
        float v = sp ? d_tab[(j + 2048) & SMASK] : d_tab[j];   // -sin / cos
        __half h = __float2half_rn(v);
        __half l = __float2half_rn(v - __half2float(h));
        if (par == 0) {
            d_Bf0h[n * 256 + c] = h; d_Bf0l[n * 256 + c] = l;
            d_BiSh[c * HS + n]  = h; d_BiSl[c * HS + n]  = l;
        } else {
            d_Bf1h[n * 256 + c] = h; d_Bf1l[n * 256 + c] = l;
            d_BiDh[c * HS + n]  = h; d_BiDl[c * HS + n]  = l;
        }
    }
}

// ---------------- spectral-weight transpose: [l,i,o,k] -> [l,k,i,o] --------
__global__ void wtrans(const float* __restrict__ swr, const float* __restrict__ swi) {
    __shared__ float t[32][33];
    const float* src = blockIdx.z ? swi : swr;
    float*       dst = blockIdx.z ? d_WTi : d_WTr;
    int k0 = blockIdx.x * 32, R0 = blockIdx.y * 32;
    t[threadIdx.y][threadIdx.x] = src[(R0 + threadIdx.y) * 256 + k0 + threadIdx.x];
    __syncthreads();
    int l = R0 >> 12, io0 = R0 & 4095;
    dst[(l * 256 + k0 + threadIdx.y) * 4096 + io0 + threadIdx.x] = t[threadIdx.x][threadIdx.y];
}

// ---------------- lifting + fold (2 elems/thread, half2 stores) -------------
__global__ void lift_fold(const float* __restrict__ u, const float* __restrict__ fc0w,
                          const float* __restrict__ fc0b,
                          __half* __restrict__ Eh, __half* __restrict__ El,
                          __half* __restrict__ Oh, __half* __restrict__ Ol) {
    int idx = blockIdx.x * 256 + threadIdx.x;   // (b*64+w)*2048 + n/2
    int n = (idx & 2047) * 2;
    int r = idx >> 11;
    int w = r & 63;
    int b = r >> 6;
    float w0 = fc0w[w], w1 = fc0w[64 + w], bb = fc0b[w];
    float2 ua = *(const float2*)&u[(size_t)b * S + n];
    float2 ub = *(const float2*)&u[(size_t)b * S + n + HS];
    const float gi = 1.0f / 8191.0f;
    float lo0 = ua.x * w0 + (float)n * gi * w1 + bb;
    float lo1 = ua.y * w0 + (float)(n + 1) * gi * w1 + bb;
    float hi0 = ub.x * w0 + (float)(n + HS) * gi * w1 + bb;
    float hi1 = ub.y * w0 + (float)(n + HS + 1) * gi * w1 + bb;
    float E0 = lo0 + hi0, E1 = lo1 + hi1;
    float O0 = lo0 - hi0, O1 = lo1 - hi1;
    size_t off = (size_t)r * HS + n;
    __half eh0 = __float2half_rn(E0), eh1 = __float2half_rn(E1);
    __half oh0 = __float2half_rn(O0), oh1 = __float2half_rn(O1);
    *(__half2*)(Eh + off) = __halves2half2(eh0, eh1);
    *(__half2*)(El + off) = __halves2half2(__float2half_rn(E0 - __half2float(eh0)),
                                           __float2half_rn(E1 - __half2float(eh1)));
    *(__half2*)(Oh + off) = __halves2half2(oh0, oh1);
    *(__half2*)(Ol + off) = __halves2half2(__float2half_rn(O0 - __half2float(oh0)),
                                           __float2half_rn(O1 - __half2float(oh1)));
}

// ---------------- forward DFT: tensor-core GEMM ----------------------------
// z=0: even modes from E; z=1: odd modes from O. C[4096x256] = A[4096x4096] @ Bf
// 2-product split: (Ah+Al) x Bh (B fp16-rounded; error ~2e-4, budget 1e-3).
__global__ __launch_bounds__(256, 1) void tc_fwd(const __half* __restrict__ Eh,
                                                 const __half* __restrict__ El,
                                                 const __half* __restrict__ Oh,
                                                 const __half* __restrict__ Ol) {
    extern __shared__ __align__(16) char smem[];
    unsigned sbase = (unsigned)__cvta_generic_to_shared(smem);
    const int tid = threadIdx.x, lane = tid & 31, warp = tid >> 5;
    const int bm = blockIdx.y, bn = blockIdx.x, z = blockIdx.z;
    const __half* gAh = (z ? Oh : Eh) + (size_t)bm * 128 * HS;
    const __half* gAl = (z ? Ol : El) + (size_t)bm * 128 * HS;
    const __half* gBh = (z ? d_Bf1h : d_Bf0h) + bn * 128;

    // stage (24KB): Ah 0..8191, Al 8192..16383, Bh 16384..24575
    auto issue = [&](int st, int k0) {
        unsigned s0 = sbase + (unsigned)st * 24576u;
        #pragma unroll
        for (int j = 0; j < 2; j++) {
            int id = tid * 2 + j;
            int r = id >> 2, c = id & 3;                       // A: 128 rows x 4 chunks
            unsigned sa = s0 + r * 64 + ((c ^ ((r >> 1) & 3)) << 4);
            size_t ga = (size_t)r * HS + k0 + c * 8;
            CP_ASYNC(sa, gAh + ga);
            CP_ASYNC(sa + 8192u, gAl + ga);
            int k = id >> 4, cc = id & 15;                     // B: 32 rows x 16 chunks
            unsigned sb = s0 + 16384u + k * 256 + ((cc ^ (k & 7)) << 4);
            size_t gb = (size_t)(k0 + k) * 256 + cc * 8;
            CP_ASYNC(sb, gBh + gb);
        }
        CP_COMMIT();
    };

    float C[2][8][4];
    #pragma unroll
    for (int i = 0; i < 2; i++)
        #pragma unroll
        for (int j = 0; j < 8; j++)
            #pragma unroll
            for (int q = 0; q < 4; q++) C[i][j][q] = 0.0f;

    const int m0w = (warp >> 1) * 32, n0w = (warp & 1) * 64;

    issue(0, 0); issue(1, 32);
    for (int i = 0; i < 128; i++) {
        CP_WAIT1();
        __syncthreads();
        if (i + 2 < 128) issue((i + 2) % 3, (i + 2) * 32);
        unsigned s0 = sbase + (unsigned)(i % 3) * 24576u;
        #pragma unroll
        for (int ks = 0; ks < 2; ks++) {
            const int kk = ks * 16;
            unsigned ah[2][4], al[2][4];
            #pragma unroll
            for (int mi = 0; mi < 2; mi++) {
                int r = m0w + mi * 16 + (lane & 15);
                int ch = (kk >> 3) + (lane >> 4);
                unsigned ad = s0 + r * 64 + ((ch ^ ((r >> 1) & 3)) << 4);
                ldsm4(ad, ah[mi]);
                ldsm4(ad + 8192u, al[mi]);
            }
            unsigned bh[8][2];
            #pragma unroll
            for (int g = 0; g < 4; g++) {
                int kr = kk + (lane & 7) + ((lane >> 3) & 1) * 8;
                int ch = ((n0w + g * 16) >> 3) + (lane >> 4);
                unsigned ad = s0 + 16384u + kr * 256 + ((ch ^ (kr & 7)) << 4);
                unsigned t[4];
                ldsm4t(ad, t);
                bh[2*g][0] = t[0]; bh[2*g][1] = t[1]; bh[2*g+1][0] = t[2]; bh[2*g+1][1] = t[3];
            }
            #pragma unroll
            for (int mi = 0; mi < 2; mi++)
                #pragma unroll
                for (int nj = 0; nj < 8; nj++) {
                    mma16816(C[mi][nj], ah[mi], bh[nj]);
                    mma16816(C[mi][nj], al[mi], bh[nj]);
                }
        }
    }
    // store into d_CT with mode remap: local col cl -> mode k=2*cl+z (Re) / Im block
    const int r0 = bm * 128 + m0w + (lane >> 2);
    const int cl0 = bn * 128 + n0w + (lane & 3) * 2;
    #pragma unroll
    for (int mi = 0; mi < 2; mi++)
        #pragma unroll
        for (int nj = 0; nj < 8; nj++) {
            int r = r0 + mi * 16;
            int cl = cl0 + nj * 8;
            int row0 = (cl < 128) ? (2 * cl + z) : (256 + 2 * (cl - 128) + z);
            d_CT[(size_t)row0 * RTOT + r]           = C[mi][nj][0];
            d_CT[(size_t)(row0 + 2) * RTOT + r]     = C[mi][nj][1];
            d_CT[(size_t)row0 * RTOT + r + 8]       = C[mi][nj][2];
            d_CT[(size_t)(row0 + 2) * RTOT + r + 8] = C[mi][nj][3];
        }
}

// ---------------- per-mode complex channel mix -> inv-GEMM A ----------------
__global__ __launch_bounds__(256) void mixk(int l) {
    extern __shared__ float sm[];
    float* Wr = sm;        float* Wi = sm + 4096;
    float* Xr = sm + 8192; float* Xi = sm + 12288;
    int k = blockIdx.x, tid = threadIdx.x;
    const float* wr = d_WTr + (size_t)(l * MODES + k) * 4096;
    const float* wi = d_WTi + (size_t)(l * MODES + k) * 4096;
    const float* cr = d_CT + (size_t)k * RTOT;
    const float* ci = d_CT + (size_t)(MODES + k) * RTOT;
    #pragma unroll
    for (int j = 0; j < 16; j++) {
        int idx = tid + 256 * j;
        Wr[idx] = wr[idx]; Wi[idx] = wi[idx];
        Xr[idx] = cr[idx]; Xi[idx] = ci[idx];
    }
    __syncthreads();
    int o = tid & 63;
    int b0 = tid >> 6;
    float ar[16], ai[16];
    #pragma unroll
    for (int j = 0; j < 16; j++) { ar[j] = 0.0f; ai[j] = 0.0f; }
    for (int i = 0; i < 64; i++) {
        float wre = Wr[i * 64 + o], wim = Wi[i * 64 + o];
        #pragma unroll
        for (int j = 0; j < 16; j++) {
            int b = b0 + 4 * j;
            float xr = Xr[b * 64 + i], xi = Xi[b * 64 + i];
            ar[j] += xr * wre - xi * wim;
            ai[j] += xr * wim + xi * wre;
        }
    }
    int par = k & 1, m = k >> 1;
    float fa = (k == 0) ? 0.5f : 1.0f;
    #pragma unroll
    for (int j = 0; j < 16; j++) {
        int lin = tid + 256 * j;                 // = b*64 + o
        size_t base = (size_t)lin * KA + par * 320;
        split_store(ar[j] * fa, &d_Ah[base + m], &d_Al[base + m]);
        split_store((k == 0) ? 0.0f : ai[j], &d_Ah[base + 128 + m], &d_Al[base + 128 + m]);
    }
}

// ---------------- pack pointwise weights into inv-GEMM A --------------------
__global__ void pwpack(const float* __restrict__ pw) {
    int idx = blockIdx.x * 256 + threadIdx.x;    // b*4096 + o*64 + i
    int i = idx & 63, o = (idx >> 6) & 63, b = idx >> 12;
    float v = pw[o * 64 + i] * 2048.0f;
    size_t base = (size_t)(b * 64 + o) * KA;
    split_store(v, &d_Ah[base + 256 + i], &d_Al[base + 256 + i]);
    split_store(v, &d_Ah[base + 576 + i], &d_Al[base + 576 + i]);
}

// ---------------- fused inverse DFT + pointwise + gelu + refold -------------
// Per (b, n-tile): acc_s = A_sum @ [BiS ; E_b], acc_d = A_dif @ [BiD ; O_b]
// y_lo = (s+d)/4096 + bias, y_hi = (s-d)/4096 + bias; emit E'=g(lo)+g(hi), O'=g(lo)-g(hi)
#define MMABLK(Cx) \
    _Pragma("unroll") \
    for (int mi = 0; mi < 2; mi++) \
        _Pragma("unroll") \
        for (int nj = 0; nj < 4; nj++) { \
            mma16816(Cx[mi][nj], ah[mi], bh[nj]); \
            mma16816(Cx[mi][nj], ah[mi], bl[nj]); \
            mma16816(Cx[mi][nj], al[mi], bh[nj]); \
        }

__global__ __launch_bounds__(256, 2) void tc_inv(const __half* __restrict__ Einh,
                                                 const __half* __restrict__ Einl,
                                                 const __half* __restrict__ Oinh,
                                                 const __half* __restrict__ Oinl,
                                                 __half* __restrict__ Eoh,
                                                 __half* __restrict__ Eol,
                                                 __half* __restrict__ Ooh,
                                                 __half* __restrict__ Ool,
                                                 const float* __restrict__ pwb,
                                                 int dogelu) {
    extern __shared__ __align__(16) char smem[];
    unsigned sbase = (unsigned)__cvta_generic_to_shared(smem);
    const int tid = threadIdx.x, lane = tid & 31, warp = tid >> 5;
    const int b = blockIdx.y;
    const int n0 = blockIdx.x * 128;
    const size_t bofs = (size_t)b * 64 * HS;
    const __half* gAh = d_Ah + (size_t)b * 64 * KA;
    const __half* gAl = d_Al + (size_t)b * 64 * KA;

    // stage (24KB): Ah 0..4095, Al 4096..8191, Bh 8192..16383, Bl 16384..24575
    auto issue = [&](int st, int c0) {
        unsigned s0 = sbase + (unsigned)st * 24576u;
        {   int r = tid >> 2, c = tid & 3;          // A: 64 rows x 4 chunks
            unsigned sa = s0 + r * 64 + ((c ^ ((r >> 1) & 3)) << 4);
            size_t ga = (size_t)r * KA + c0 + c * 8;
            CP_ASYNC(sa, gAh + ga);
            CP_ASYNC(sa + 4096u, gAl + ga);
        }
        #pragma unroll
        for (int j = 0; j < 2; j++) {
            int id = tid * 2 + j;
            int k = id >> 4, cc = id & 15;          // B: 32 rows x 16 chunks
            int cg = c0 + k;
            const __half *ph, *pl;
            if (cg < 256)      { size_t o = (size_t)cg * HS + n0 + cc * 8;          ph = d_BiSh + o;       pl = d_BiSl + o; }
            else if (cg < 320) { size_t o = (size_t)(cg - 256) * HS + n0 + cc * 8;  ph = Einh + bofs + o;  pl = Einl + bofs + o; }
            else if (cg < 576) { size_t o = (size_t)(cg - 320) * HS + n0 + cc * 8;  ph = d_BiDh + o;       pl = d_BiDl + o; }
            else               { size_t o = (size_t)(cg - 576) * HS + n0 + cc * 8;  ph = Oinh + bofs + o;  pl = Oinl + bofs + o; }
            unsigned sb = s0 + 8192u + k * 256 + ((cc ^ (k & 7)) << 4);
            CP_ASYNC(sb, ph);
            CP_ASYNC(sb + 8192u, pl);
        }
        CP_COMMIT();
    };

    float Cs[2][4][4], Cd[2][4][4];
    #pragma unroll
    for (int i = 0; i < 2; i++)
        #pragma unroll
        for (int j = 0; j < 4; j++)
            #pragma unroll
            for (int q = 0; q < 4; q++) { Cs[i][j][q] = 0.0f; Cd[i][j][q] = 0.0f; }

    const int m0w = (warp >> 2) * 32, n0w = (warp & 3) * 32;

    issue(0, 0); issue(1, 32);
    for (int i = 0; i < 20; i++) {
        CP_WAIT1();
        __syncthreads();
        if (i + 2 < 20) issue((i + 2) % 3, (i + 2) * 32);
        unsigned s0 = sbase + (unsigned)(i % 3) * 24576u;
        #pragma unroll
        for (int ks = 0; ks < 2; ks++) {
            const int kk = ks * 16;
            unsigned ah[2][4], al[2][4];
            #pragma unroll
            for (int mi = 0; mi < 2; mi++) {
                int r = m0w + mi * 16 + (lane & 15);
                int ch = (kk >> 3) + (lane >> 4);
                unsigned ad = s0 + r * 64 + ((ch ^ ((r >> 1) & 3)) << 4);
                ldsm4(ad, ah[mi]);
                ldsm4(ad + 4096u, al[mi]);
            }
            unsigned bh[4][2], bl[4][2];
            #pragma unroll
            for (int g = 0; g < 2; g++) {
                int kr = kk + (lane & 7) + ((lane >> 3) & 1) * 8;
                int ch = ((n0w + g * 16) >> 3) + (lane >> 4);
                unsigned ad = s0 + 8192u + kr * 256 + ((ch ^ (kr & 7)) << 4);
                unsigned t[4];
                ldsm4t(ad, t);
                bh[2*g][0] = t[0]; bh[2*g][1] = t[1]; bh[2*g+1][0] = t[2]; bh[2*g+1][1] = t[3];
                ldsm4t(ad + 8192u, t);
                bl[2*g][0] = t[0]; bl[2*g][1] = t[1]; bl[2*g+1][0] = t[2]; bl[2*g+1][1] = t[3];
            }
            if (i < 10) { MMABLK(Cs) } else { MMABLK(Cd) }
        }
    }
    // epilogue
    const int o0 = m0w + (lane >> 2);
    const int nl0 = n0w + (lane & 3) * 2;
    #pragma unroll
    for (int mi = 0; mi < 2; mi++)
        #pragma unroll
        for (int h = 0; h < 2; h++) {
            int o = o0 + mi * 16 + h * 8;
            float bias = pwb[o];
            size_t rowo = ((size_t)(b * 64 + o)) * HS;
            #pragma unroll
            for (int nj = 0; nj < 4; nj++) {
                int ng = n0 + nl0 + nj * 8;
                float s0v = Cs[mi][nj][h * 2],     d0v = Cd[mi][nj][h * 2];
                float s1v = Cs[mi][nj][h * 2 + 1], d1v = Cd[mi][nj][h * 2 + 1];
                float ylo0 = (s0v + d0v) * INV_SCALE + bias;
                float yhi0 = (s0v - d0v) * INV_SCALE + bias;
                float ylo1 = (s1v + d1v) * INV_SCALE + bias;
                float yhi1 = (s1v - d1v) * INV_SCALE + bias;
                if (dogelu) {
                    ylo0 = gelu_f(ylo0); yhi0 = gelu_f(yhi0);
                    ylo1 = gelu_f(ylo1); yhi1 = gelu_f(yhi1);
                }
                float E0 = ylo0 + yhi0, O0 = ylo0 - yhi0;
                float E1 = ylo1 + yhi1, O1 = ylo1 - yhi1;
                __half eh0 = __float2half_rn(E0), eh1 = __float2half_rn(E1);
                __half el0 = __float2half_rn(E0 - __half2float(eh0));
                __half el1 = __float2half_rn(E1 - __half2float(eh1));
                __half oh0 = __float2half_rn(O0), oh1 = __float2half_rn(O1);
                __half ol0 = __float2half_rn(O0 - __half2float(oh0));
                __half ol1 = __float2half_rn(O1 - __half2float(oh1));
                *(__half2*)(Eoh + rowo + ng) = __halves2half2(eh0, eh1);
                *(__half2*)(Eol + rowo + ng) = __halves2half2(el0, el1);
                *(__half2*)(Ooh + rowo + ng) = __halves2half2(oh0, oh1);
                *(__half2*)(Ool + rowo + ng) = __halves2half2(ol0, ol1);
            }
        }
}

// ---------------- head: gelu(x^T @ fc1 + b1) @ fc2 + b2 --------------------
__global__ __launch_bounds__(256) void headk(const __half* __restrict__ Eh,
                                             const __half* __restrict__ El,
                                             const __half* __restrict__ Oh,
                                             const __half* __restrict__ Ol,
                                             const float* __restrict__ fc1w,
                                             const float* __restrict__ fc1b,
                                             const float* __restrict__ fc2w,
                                             const float* __restrict__ fc2b,
                                             float* __restrict__ out) {
    extern __shared__ float sm[];
    float* fc1s = sm;            // [64][128]
    float* xs   = sm + 8192;     // [64][128], reused for reduction
    float* b1s  = sm + 16384;    // [128]
    float* fc2s = sm + 16512;    // [128]
    int b = blockIdx.y;
    int s0 = blockIdx.x * 128;
    int tid = threadIdx.x;
    int hi = (s0 >= HS);
    int sh = s0 & (HS - 1);
    #pragma unroll
    for (int j = 0; j < 32; j++) {
        int idx = tid + 256 * j;
        fc1s[idx] = fc1w[idx];
        size_t off = (size_t)(b * 64 + (idx >> 7)) * HS + sh + (idx & 127);
        float e = __half2float(Eh[off]) + __half2float(El[off]);
        float o = __half2float(Oh[off]) + __half2float(Ol[off]);
        xs[idx] = 0.5f * (hi ? (e - o) : (e + o));
    }
    if (tid < 128) { b1s[tid] = fc1b[tid]; fc2s[tid] = fc2w[tid]; }
    __syncthreads();

    int tm = tid >> 4, tn = tid & 15;
    float acc[8][8];
    #pragma unroll
    for (int i = 0; i < 8; i++)
        #pragma unroll
        for (int j = 0; j < 8; j++) acc[i][j] = 0.0f;
    for (int i = 0; i < 64; i++) {
        float av[8], bv[8];
        #pragma unroll
        for (int ii = 0; ii < 8; ii++) av[ii] = xs[i * 128 + tm * 8 + ii];
        #pragma unroll
        for (int jj = 0; jj < 8; jj++) bv[jj] = fc1s[i * 128 + tn * 8 + jj];
        #pragma unroll
        for (int ii = 0; ii < 8; ii++)
            #pragma unroll
            for (int jj = 0; jj < 8; jj++) acc[ii][jj] += av[ii] * bv[jj];
    }
    float part[8];
    #pragma unroll
    for (int ii = 0; ii < 8; ii++) {
        float p = 0.0f;
        #pragma unroll
        for (int jj = 0; jj < 8; jj++) {
            float h = gelu_f(acc[ii][jj] + b1s[tn * 8 + jj]);
            p += h * fc2s[tn * 8 + jj];
        }
        part[ii] = p;
    }
    __syncthreads();
    float* red = xs;
    #pragma unroll
    for (int ii = 0; ii < 8; ii++) red[(tm * 8 + ii) * 16 + tn] = part[ii];
    __syncthreads();
    if (tid < 128) {
        float ssum = fc2b[0];
        #pragma unroll
        for (int t = 0; t < 16; t++) ssum += red[tid * 16 + t];
        out[(size_t)b * S + s0 + tid] = ssum;
    }
}

// ---------------------------------------------------------------------------
extern "C" void kernel_launch(void* const* d_in, const int* in_sizes, int n_in,
                              void* d_out, int out_size) {
    const float* u    = (const float*)d_in[0];
    const float* fc0w = (const float*)d_in[1];
    const float* fc0b = (const float*)d_in[2];
    const float* swr  = (const float*)d_in[3];
    const float* swi  = (const float*)d_in[4];
    const float* pww  = (const float*)d_in[5];
    const float* pwb  = (const float*)d_in[6];
    const float* fc1w = (const float*)d_in[7];
    const float* fc1b = (const float*)d_in[8];
    const float* fc2w = (const float*)d_in[9];
    const float* fc2b = (const float*)d_in[10];
    float* out = (float*)d_out;

    cudaFuncSetAttribute(mixk,   cudaFuncAttributeMaxDynamicSharedMemorySize, 65536);
    cudaFuncSetAttribute(headk,  cudaFuncAttributeMaxDynamicSharedMemorySize, 66560);
    cudaFuncSetAttribute(tc_fwd, cudaFuncAttributeMaxDynamicSharedMemorySize, 73728);
    cudaFuncSetAttribute(tc_inv, cudaFuncAttributeMaxDynamicSharedMemorySize, 73728);

    __half *pE0h, *pE0l, *pO0h, *pO0l, *pE1h, *pE1l, *pO1h, *pO1l;
    cudaGetSymbolAddress((void**)&pE0h, d_E0h);
    cudaGetSymbolAddress((void**)&pE0l, d_E0l);
    cudaGetSymbolAddress((void**)&pO0h, d_O0h);
    cudaGetSymbolAddress((void**)&pO0l, d_O0l);
    cudaGetSymbolAddress((void**)&pE1h, d_E1h);
    cudaGetSymbolAddress((void**)&pE1l, d_E1l);
    cudaGetSymbolAddress((void**)&pO1h, d_O1h);
    cudaGetSymbolAddress((void**)&pO1l, d_O1l);

    gen_table<<<32, 256>>>();
    gen_basis<<<4096, 256>>>();
    wtrans<<<dim3(8, 512, 2), dim3(32, 32)>>>(swr, swi);
    lift_fold<<<32768, 256>>>(u, fc0w, fc0b, pE0h, pE0l, pO0h, pO0l);

    __half *Eih = pE0h, *Eil = pE0l, *Oih = pO0h, *Oil = pO0l;
    __half *Eoh = pE1h, *Eol = pE1l, *Ooh = pO1h, *Ool = pO1l;
    for (int l = 0; l < 4; l++) {
        tc_fwd<<<dim3(2, 32, 2), 256, 73728>>>(Eih, Eil, Oih, Oil);
        mixk<<<256, 256, 65536>>>(l);
        pwpack<<<1024, 256>>>(pww + l * W * W);
        tc_inv<<<dim3(32, 64), 256, 73728>>>(Eih, Eil, Oih, Oil,
                                             Eoh, Eol, Ooh, Ool,
                                             pwb + l * W, (l < 3) ? 1 : 0);
        __half* t;
        t = Eih; Eih = Eoh; Eoh = t;
        t = Eil; Eil = Eol; Eol = t;
        t = Oih; Oih = Ooh; Ooh = t;
        t = Oil; Oil = Ool; Ool = t;
    }
    headk<<<dim3(64, 64), 256, 66560>>>(Eih, Eil, Oih, Oil,
                                        fc1w, fc1b, fc2w, fc2b, out);
}

// round 15
// speedup vs baseline: 1.1778x; 1.0518x over previous
#include <cuda_runtime.h>
#include <cuda_fp16.h>
#include <math.h>

#define S     8192
#define SMASK 8191
#define HS    4096      // S/2
#define W     64
#define MODES 256
#define RTOT  4096      // 64 batches * 64 channels
#define KA    640       // inv-GEMM A width: (128re+128im+64pw) even + same odd
#define INV_SCALE 0.000244140625f   // 1/4096

// ---------------- scratch (device globals; no allocations) ----------------
__device__ __half d_E0h[RTOT * HS], d_E0l[RTOT * HS];
__device__ __half d_O0h[RTOT * HS], d_O0l[RTOT * HS];
__device__ __half d_E1h[RTOT * HS], d_E1l[RTOT * HS];
__device__ __half d_O1h[RTOT * HS], d_O1l[RTOT * HS];
__device__ __half d_Bf0h[HS * 256], d_Bf0l[HS * 256];   // fwd basis even modes [n][c]
__device__ __half d_Bf1h[HS * 256], d_Bf1l[HS * 256];   // fwd basis odd  modes [n][c]
__device__ __half d_BiSh[256 * HS], d_BiSl[256 * HS];   // inv basis even [c][n]
__device__ __half d_BiDh[256 * HS], d_BiDl[256 * HS];   // inv basis odd  [c][n]
__device__ float  d_CT[512 * RTOT];                     // fwd out, [c][r]
__device__ __half d_Ah[RTOT * KA], d_Al[RTOT * KA];     // inv-GEMM A
__device__ float  d_WTr[4 * 256 * 64 * 64];             // spectral W re [l][k][i][o]
__device__ float  d_WTi[4 * 256 * 64 * 64];             // spectral W im
__device__ float  d_tab[8192];                          // cos table

__device__ __forceinline__ float gelu_f(float x) {
    return 0.5f * x * (1.0f + erff(x * 0.7071067811865476f));
}

// ---------------- PTX helpers ----------------------------------------------
#define CP_ASYNC(dst, src) \
    asm volatile("cp.async.cg.shared.global [%0], [%1], 16;" :: "r"(dst), "l"(src))
#define CP_COMMIT() asm volatile("cp.async.commit_group;")
#define CP_WAIT1()  asm volatile("cp.async.wait_group 1;")
#define CP_WAIT0()  asm volatile("cp.async.wait_group 0;")

__device__ __forceinline__ void ldsm4(unsigned a, unsigned* r) {
    asm volatile("ldmatrix.sync.aligned.m8n8.x4.shared.b16 {%0,%1,%2,%3}, [%4];"
                 : "=r"(r[0]), "=r"(r[1]), "=r"(r[2]), "=r"(r[3]) : "r"(a));
}
__device__ __forceinline__ void ldsm4t(unsigned a, unsigned* r) {
    asm volatile("ldmatrix.sync.aligned.m8n8.x4.trans.shared.b16 {%0,%1,%2,%3}, [%4];"
                 : "=r"(r[0]), "=r"(r[1]), "=r"(r[2]), "=r"(r[3]) : "r"(a));
}
__device__ __forceinline__ void mma16816(float* c, const unsigned* a, const unsigned* b) {
    asm volatile("mma.sync.aligned.m16n8k16.row.col.f32.f16.f16.f32 "
                 "{%0,%1,%2,%3}, {%4,%5,%6,%7}, {%8,%9}, {%0,%1,%2,%3};"
                 : "+f"(c[0]), "+f"(c[1]), "+f"(c[2]), "+f"(c[3])
                 : "r"(a[0]), "r"(a[1]), "r"(a[2]), "r"(a[3]), "r"(b[0]), "r"(b[1]));
}
__device__ __forceinline__ void split_store(float v, __half* ph, __half* pl) {
    __half h = __float2half_rn(v);
    *ph = h;
    *pl = __float2half_rn(v - __half2float(h));
}

// ---------------- basis via cos table ---------------------------------------
__global__ void gen_table() {
    int j = blockIdx.x * 256 + threadIdx.x;
    d_tab[j] = cospif((float)j * (1.0f / 4096.0f));
}
__global__ void gen_basis() {
    int idx = blockIdx.x * 256 + threadIdx.x;   // n*256 + c
    int n = idx >> 8, c = idx & 255, m = c & 127;
    bool sp = (c >= 128);
    #pragma unroll
    for (int par = 0; par < 2; par++) {
        int k = 2 * m + par;
        int j = (k * n) & SMASK;
        float v = sp ? d_tab[(j + 2048) & SMASK] : d_tab[j];   // -sin / cos
        __half h = __float2half_rn(v);
        __half l = __float2half_rn(v - __half2float(h));
        if (par == 0) {
            d_Bf0h[n * 256 + c] = h; d_Bf0l[n * 256 + c] = l;
            d_BiSh[c * HS + n]  = h; d_BiSl[c * HS + n]  = l;
        } else {
            d_Bf1h[n * 256 + c] = h; d_Bf1l[n * 256 + c] = l;
            d_BiDh[c * HS + n]  = h; d_BiDl[c * HS + n]  = l;
        }
    }
}

// ---------------- spectral-weight transpose: [l,i,o,k] -> [l,k,i,o] --------
__global__ void wtrans(const float* __restrict__ swr, const float* __restrict__ swi) {
    __shared__ float t[32][33];
    const float* src = blockIdx.z ? swi : swr;
    float*       dst = blockIdx.z ? d_WTi : d_WTr;
    int k0 = blockIdx.x * 32, R0 = blockIdx.y * 32;
    t[threadIdx.y][threadIdx.x] = src[(R0 + threadIdx.y) * 256 + k0 + threadIdx.x];
    __syncthreads();
    int l = R0 >> 12, io0 = R0 & 4095;
    dst[(l * 256 + k0 + threadIdx.y) * 4096 + io0 + threadIdx.x] = t[threadIdx.x][threadIdx.y];
}

// ---------------- lifting + fold (2 elems/thread, half2 stores) -------------
__global__ void lift_fold(const float* __restrict__ u, const float* __restrict__ fc0w,
                          const float* __restrict__ fc0b,
                          __half* __restrict__ Eh, __half* __restrict__ El,
                          __half* __restrict__ Oh, __half* __restrict__ Ol) {
    int idx = blockIdx.x * 256 + threadIdx.x;   // (b*64+w)*2048 + n/2
    int n = (idx & 2047) * 2;
    int r = idx >> 11;
    int w = r & 63;
    int b = r >> 6;
    float w0 = fc0w[w], w1 = fc0w[64 + w], bb = fc0b[w];
    float2 ua = *(const float2*)&u[(size_t)b * S + n];
    float2 ub = *(const float2*)&u[(size_t)b * S + n + HS];
    const float gi = 1.0f / 8191.0f;
    float lo0 = ua.x * w0 + (float)n * gi * w1 + bb;
    float lo1 = ua.y * w0 + (float)(n + 1) * gi * w1 + bb;
    float hi0 = ub.x * w0 + (float)(n + HS) * gi * w1 + bb;
    float hi1 = ub.y * w0 + (float)(n + HS + 1) * gi * w1 + bb;
    float E0 = lo0 + hi0, E1 = lo1 + hi1;
    float O0 = lo0 - hi0, O1 = lo1 - hi1;
    size_t off = (size_t)r * HS + n;
    __half eh0 = __float2half_rn(E0), eh1 = __float2half_rn(E1);
    __half oh0 = __float2half_rn(O0), oh1 = __float2half_rn(O1);
    *(__half2*)(Eh + off) = __halves2half2(eh0, eh1);
    *(__half2*)(El + off) = __halves2half2(__float2half_rn(E0 - __half2float(eh0)),
                                           __float2half_rn(E1 - __half2float(eh1)));
    *(__half2*)(Oh + off) = __halves2half2(oh0, oh1);
    *(__half2*)(Ol + off) = __halves2half2(__float2half_rn(O0 - __half2float(oh0)),
                                           __float2half_rn(O1 - __half2float(oh1)));
}

// ---------------- forward DFT: tensor-core GEMM ----------------------------
// z=0: even modes from E; z=1: odd modes from O. C[4096x256] = A[4096x4096] @ Bf
// 2-product split: (Ah+Al) x Bh. Final-iteration wait_group 0 closes the
// last-stage cp.async race.
__global__ __launch_bounds__(256, 1) void tc_fwd(const __half* __restrict__ Eh,
                                                 const __half* __restrict__ El,
                                                 const __half* __restrict__ Oh,
                                                 const __half* __restrict__ Ol) {
    extern __shared__ __align__(16) char smem[];
    unsigned sbase = (unsigned)__cvta_generic_to_shared(smem);
    const int tid = threadIdx.x, lane = tid & 31, warp = tid >> 5;
    const int bm = blockIdx.y, bn = blockIdx.x, z = blockIdx.z;
    const __half* gAh = (z ? Oh : Eh) + (size_t)bm * 128 * HS;
    const __half* gAl = (z ? Ol : El) + (size_t)bm * 128 * HS;
    const __half* gBh = (z ? d_Bf1h : d_Bf0h) + bn * 128;

    // stage (24KB): Ah 0..8191, Al 8192..16383, Bh 16384..24575
    auto issue = [&](int st, int k0) {
        unsigned s0 = sbase + (unsigned)st * 24576u;
        #pragma unroll
        for (int j = 0; j < 2; j++) {
            int id = tid * 2 + j;
            int r = id >> 2, c = id & 3;                       // A: 128 rows x 4 chunks
            unsigned sa = s0 + r * 64 + ((c ^ ((r >> 1) & 3)) << 4);
            size_t ga = (size_t)r * HS + k0 + c * 8;
            CP_ASYNC(sa, gAh + ga);
            CP_ASYNC(sa + 8192u, gAl + ga);
            int k = id >> 4, cc = id & 15;                     // B: 32 rows x 16 chunks
            unsigned sb = s0 + 16384u + k * 256 + ((cc ^ (k & 7)) << 4);
            size_t gb = (size_t)(k0 + k) * 256 + cc * 8;
            CP_ASYNC(sb, gBh + gb);
        }
        CP_COMMIT();
    };

    float C[2][8][4];
    #pragma unroll
    for (int i = 0; i < 2; i++)
        #pragma unroll
        for (int j = 0; j < 8; j++)
            #pragma unroll
            for (int q = 0; q < 4; q++) C[i][j][q] = 0.0f;

    const int m0w = (warp >> 1) * 32, n0w = (warp & 1) * 64;

    issue(0, 0); issue(1, 32);
    for (int i = 0; i < 128; i++) {
        if (i < 127) { CP_WAIT1(); } else { CP_WAIT0(); }
        __syncthreads();
        if (i + 2 < 128) issue((i + 2) % 3, (i + 2) * 32);
        unsigned s0 = sbase + (unsigned)(i % 3) * 24576u;
        #pragma unroll
        for (int ks = 0; ks < 2; ks++) {
            const int kk = ks * 16;
            unsigned ah[2][4], al[2][4];
            #pragma unroll
            for (int mi = 0; mi < 2; mi++) {
                int r = m0w + mi * 16 + (lane & 15);
                int ch = (kk >> 3) + (lane >> 4);
                unsigned ad = s0 + r * 64 + ((ch ^ ((r >> 1) & 3)) << 4);
                ldsm4(ad, ah[mi]);
                ldsm4(ad + 8192u, al[mi]);
            }
            unsigned bh[8][2];
            #pragma unroll
            for (int g = 0; g < 4; g++) {
                int kr = kk + (lane & 7) + ((lane >> 3) & 1) * 8;
                int ch = ((n0w + g * 16) >> 3) + (lane >> 4);
                unsigned ad = s0 + 16384u + kr * 256 + ((ch ^ (kr & 7)) << 4);
                unsigned t[4];
                ldsm4t(ad, t);
                bh[2*g][0] = t[0]; bh[2*g][1] = t[1]; bh[2*g+1][0] = t[2]; bh[2*g+1][1] = t[3];
            }
            #pragma unroll
            for (int mi = 0; mi < 2; mi++)
                #pragma unroll
                for (int nj = 0; nj < 8; nj++) {
                    mma16816(C[mi][nj], ah[mi], bh[nj]);
                    mma16816(C[mi][nj], al[mi], bh[nj]);
                }
        }
    }
    // store into d_CT with mode remap: local col cl -> mode k=2*cl+z (Re) / Im block
    const int r0 = bm * 128 + m0w + (lane >> 2);
    const int cl0 = bn * 128 + n0w + (lane & 3) * 2;
    #pragma unroll
    for (int mi = 0; mi < 2; mi++)
        #pragma unroll
        for (int nj = 0; nj < 8; nj++) {
            int r = r0 + mi * 16;
            int cl = cl0 + nj * 8;
            int row0 = (cl < 128) ? (2 * cl + z) : (256 + 2 * (cl - 128) + z);
            d_CT[(size_t)row0 * RTOT + r]           = C[mi][nj][0];
            d_CT[(size_t)(row0 + 2) * RTOT + r]     = C[mi][nj][1];
            d_CT[(size_t)row0 * RTOT + r + 8]       = C[mi][nj][2];
            d_CT[(size_t)(row0 + 2) * RTOT + r + 8] = C[mi][nj][3];
        }
}

// ---------------- per-mode complex channel mix -> inv-GEMM A ----------------
__global__ __launch_bounds__(256) void mixk(int l) {
    extern __shared__ float sm[];
    float* Wr = sm;        float* Wi = sm + 4096;
    float* Xr = sm + 8192; float* Xi = sm + 12288;
    int k = blockIdx.x, tid = threadIdx.x;
    const float* wr = d_WTr + (size_t)(l * MODES + k) * 4096;
    const float* wi = d_WTi + (size_t)(l * MODES + k) * 4096;
    const float* cr = d_CT + (size_t)k * RTOT;
    const float* ci = d_CT + (size_t)(MODES + k) * RTOT;
    #pragma unroll
    for (int j = 0; j < 16; j++) {
        int idx = tid + 256 * j;
        Wr[idx] = wr[idx]; Wi[idx] = wi[idx];
        Xr[idx] = cr[idx]; Xi[idx] = ci[idx];
    }
    __syncthreads();
    int o = tid & 63;
    int b0 = tid >> 6;
    float ar[16], ai[16];
    #pragma unroll
    for (int j = 0; j < 16; j++) { ar[j] = 0.0f; ai[j] = 0.0f; }
    for (int i = 0; i < 64; i++) {
        float wre = Wr[i * 64 + o], wim = Wi[i * 64 + o];
        #pragma unroll
        for (int j = 0; j < 16; j++) {
            int b = b0 + 4 * j;
            float xr = Xr[b * 64 + i], xi = Xi[b * 64 + i];
            ar[j] += xr * wre - xi * wim;
            ai[j] += xr * wim + xi * wre;
        }
    }
    int par = k & 1, m = k >> 1;
    float fa = (k == 0) ? 0.5f : 1.0f;
    #pragma unroll
    for (int j = 0; j < 16; j++) {
        int lin = tid + 256 * j;                 // = b*64 + o
        size_t base = (size_t)lin * KA + par * 320;
        split_store(ar[j] * fa, &d_Ah[base + m], &d_Al[base + m]);
        split_store((k == 0) ? 0.0f : ai[j], &d_Ah[base + 128 + m], &d_Al[base + 128 + m]);
    }
}

// ---------------- pack pointwise weights into inv-GEMM A --------------------
__global__ void pwpack(const float* __restrict__ pw) {
    int idx = blockIdx.x * 256 + threadIdx.x;    // b*4096 + o*64 + i
    int i = idx & 63, o = (idx >> 6) & 63, b = idx >> 12;
    float v = pw[o * 64 + i] * 2048.0f;
    size_t base = (size_t)(b * 64 + o) * KA;
    split_store(v, &d_Ah[base + 256 + i], &d_Al[base + 256 + i]);
    split_store(v, &d_Ah[base + 576 + i], &d_Al[base + 576 + i]);
}

// ---------------- fused inverse DFT + pointwise + gelu + refold -------------
// Basis chunks: 2 products (Ah+Al)xBh. Activation chunks (pw path): 3 products.
// Final-iteration wait_group 0 closes the last-stage cp.async race.
#define MMABLK3(Cx) \
    _Pragma("unroll") \
    for (int mi = 0; mi < 2; mi++) \
        _Pragma("unroll") \
        for (int nj = 0; nj < 4; nj++) { \
            mma16816(Cx[mi][nj], ah[mi], bh[nj]); \
            mma16816(Cx[mi][nj], ah[mi], bl[nj]); \
            mma16816(Cx[mi][nj], al[mi], bh[nj]); \
        }
#define MMABLK2(Cx) \
    _Pragma("unroll") \
    for (int mi = 0; mi < 2; mi++) \
        _Pragma("unroll") \
        for (int nj = 0; nj < 4; nj++) { \
            mma16816(Cx[mi][nj], ah[mi], bh[nj]); \
            mma16816(Cx[mi][nj], al[mi], bh[nj]); \
        }

__global__ __launch_bounds__(256, 2) void tc_inv(const __half* __restrict__ Einh,
                                                 const __half* __restrict__ Einl,
                                                 const __half* __restrict__ Oinh,
                                                 const __half* __restrict__ Oinl,
                                                 __half* __restrict__ Eoh,
                                                 __half* __restrict__ Eol,
                                                 __half* __restrict__ Ooh,
                                                 __half* __restrict__ Ool,
                                                 const float* __restrict__ pwb,
                                                 int dogelu) {
    extern __shared__ __align__(16) char smem[];
    unsigned sbase = (unsigned)__cvta_generic_to_shared(smem);
    const int tid = threadIdx.x, lane = tid & 31, warp = tid >> 5;
    const int b = blockIdx.y;
    const int n0 = blockIdx.x * 128;
    const size_t bofs = (size_t)b * 64 * HS;
    const __half* gAh = d_Ah + (size_t)b * 64 * KA;
    const __half* gAl = d_Al + (size_t)b * 64 * KA;

    // stage (24KB): Ah 0..4095, Al 4096..8191, Bh 8192..16383, Bl 16384..24575
    auto issue = [&](int st, int c0) {
        unsigned s0 = sbase + (unsigned)st * 24576u;
        {   int r = tid >> 2, c = tid & 3;          // A: 64 rows x 4 chunks
            unsigned sa = s0 + r * 64 + ((c ^ ((r >> 1) & 3)) << 4);
            size_t ga = (size_t)r * KA + c0 + c * 8;
            CP_ASYNC(sa, gAh + ga);
            CP_ASYNC(sa + 4096u, gAl + ga);
        }
        #pragma unroll
        for (int j = 0; j < 2; j++) {
            int id = tid * 2 + j;
            int k = id >> 4, cc = id & 15;          // B: 32 rows x 16 chunks
            int cg = c0 + k;
            const __half *ph, *pl;
            if (cg < 256)      { size_t o = (size_t)cg * HS + n0 + cc * 8;          ph = d_BiSh + o;       pl = d_BiSl + o; }
            else if (cg < 320) { size_t o = (size_t)(cg - 256) * HS + n0 + cc * 8;  ph = Einh + bofs + o;  pl = Einl + bofs + o; }
            else if (cg < 576) { size_t o = (size_t)(cg - 320) * HS + n0 + cc * 8;  ph = d_BiDh + o;       pl = d_BiDl + o; }
            else               { size_t o = (size_t)(cg - 576) * HS + n0 + cc * 8;  ph = Oinh + bofs + o;  pl = Oinl + bofs + o; }
            unsigned sb = s0 + 8192u + k * 256 + ((cc ^ (k & 7)) << 4);
            CP_ASYNC(sb, ph);
            CP_ASYNC(sb + 8192u, pl);
        }
        CP_COMMIT();
    };

    float Cs[2][4][4], Cd[2][4][4];
    #pragma unroll
    for (int i = 0; i < 2; i++)
        #pragma unroll
        for (int j = 0; j < 4; j++)
            #pragma unroll
            for (int q = 0; q < 4; q++) { Cs[i][j][q] = 0.0f; Cd[i][j][q] = 0.0f; }

    const int m0w = (warp >> 2) * 32, n0w = (warp & 3) * 32;

    issue(0, 0); issue(1, 32);
    for (int i = 0; i < 20; i++) {
        if (i < 19) { CP_WAIT1(); } else { CP_WAIT0(); }
        __syncthreads();
        if (i + 2 < 20) issue((i + 2) % 3, (i + 2) * 32);
        unsigned s0 = sbase + (unsigned)(i % 3) * 24576u;
        const bool act = (i == 8) || (i == 9) || (i == 18) || (i == 19);
        #pragma unroll
        for (int ks = 0; ks < 2; ks++) {
            const int kk = ks * 16;
            unsigned ah[2][4], al[2][4];
            #pragma unroll
            for (int mi = 0; mi < 2; mi++) {
                int r = m0w + mi * 16 + (lane & 15);
                int ch = (kk >> 3) + (lane >> 4);
                unsigned ad = s0 + r * 64 + ((ch ^ ((r >> 1) & 3)) << 4);
                ldsm4(ad, ah[mi]);
                ldsm4(ad + 4096u, al[mi]);
            }
            unsigned bh[4][2], bl[4][2];
            #pragma unroll
            for (int g = 0; g < 2; g++) {
                int kr = kk + (lane & 7) + ((lane >> 3) & 1) * 8;
                int ch = ((n0w + g * 16) >> 3) + (lane >> 4);
                unsigned ad = s0 + 8192u + kr * 256 + ((ch ^ (kr & 7)) << 4);
                unsigned t[4];
                ldsm4t(ad, t);
                bh[2*g][0] = t[0]; bh[2*g][1] = t[1]; bh[2*g+1][0] = t[2]; bh[2*g+1][1] = t[3];
                if (act) {
                    ldsm4t(ad + 8192u, t);
                    bl[2*g][0] = t[0]; bl[2*g][1] = t[1]; bl[2*g+1][0] = t[2]; bl[2*g+1][1] = t[3];
                }
            }
            if (i < 10) {
                if (act) { MMABLK3(Cs) } else { MMABLK2(Cs) }
            } else {
                if (act) { MMABLK3(Cd) } else { MMABLK2(Cd) }
            }
        }
    }
    // epilogue
    const int o0 = m0w + (lane >> 2);
    const int nl0 = n0w + (lane & 3) * 2;
    #pragma unroll
    for (int mi = 0; mi < 2; mi++)
        #pragma unroll
        for (int h = 0; h < 2; h++) {
            int o = o0 + mi * 16 + h * 8;
            float bias = pwb[o];
            size_t rowo = ((size_t)(b * 64 + o)) * HS;
            #pragma unroll
            for (int nj = 0; nj < 4; nj++) {
                int ng = n0 + nl0 + nj * 8;
                float s0v = Cs[mi][nj][h * 2],     d0v = Cd[mi][nj][h * 2];
                float s1v = Cs[mi][nj][h * 2 + 1], d1v = Cd[mi][nj][h * 2 + 1];
                float ylo0 = (s0v + d0v) * INV_SCALE + bias;
                float yhi0 = (s0v - d0v) * INV_SCALE + bias;
                float ylo1 = (s1v + d1v) * INV_SCALE + bias;
                float yhi1 = (s1v - d1v) * INV_SCALE + bias;
                if (dogelu) {
                    ylo0 = gelu_f(ylo0); yhi0 = gelu_f(yhi0);
                    ylo1 = gelu_f(ylo1); yhi1 = gelu_f(yhi1);
                }
                float E0 = ylo0 + yhi0, O0 = ylo0 - yhi0;
                float E1 = ylo1 + yhi1, O1 = ylo1 - yhi1;
                __half eh0 = __float2half_rn(E0), eh1 = __float2half_rn(E1);
                __half el0 = __float2half_rn(E0 - __half2float(eh0));
                __half el1 = __float2half_rn(E1 - __half2float(eh1));
                __half oh0 = __float2half_rn(O0), oh1 = __float2half_rn(O1);
                __half ol0 = __float2half_rn(O0 - __half2float(oh0));
                __half ol1 = __float2half_rn(O1 - __half2float(oh1));
                *(__half2*)(Eoh + rowo + ng) = __halves2half2(eh0, eh1);
                *(__half2*)(Eol + rowo + ng) = __halves2half2(el0, el1);
                *(__half2*)(Ooh + rowo + ng) = __halves2half2(oh0, oh1);
                *(__half2*)(Ool + rowo + ng) = __halves2half2(ol0, ol1);
            }
        }
}

// ---------------- head: gelu(x^T @ fc1 + b1) @ fc2 + b2 --------------------
__global__ __launch_bounds__(256) void headk(const __half* __restrict__ Eh,
                                             const __half* __restrict__ El,
                                             const __half* __restrict__ Oh,
                                             const __half* __restrict__ Ol,
                                             const float* __restrict__ fc1w,
                                             const float* __restrict__ fc1b,
                                             const float* __restrict__ fc2w,
                                             const float* __restrict__ fc2b,
                                             float* __restrict__ out) {
    extern __shared__ float sm[];
    float* fc1s = sm;            // [64][128]
    float* xs   = sm + 8192;     // [64][128], reused for reduction
    float* b1s  = sm + 16384;    // [128]
    float* fc2s = sm + 16512;    // [128]
    int b = blockIdx.y;
    int s0 = blockIdx.x * 128;
    int tid = threadIdx.x;
    int hi = (s0 >= HS);
    int sh = s0 & (HS - 1);
    #pragma unroll
    for (int j = 0; j < 32; j++) {
        int idx = tid + 256 * j;
        fc1s[idx] = fc1w[idx];
        size_t off = (size_t)(b * 64 + (idx >> 7)) * HS + sh + (idx & 127);
        float e = __half2float(Eh[off]) + __half2float(El[off]);
        float o = __half2float(Oh[off]) + __half2float(Ol[off]);
        xs[idx] = 0.5f * (hi ? (e - o) : (e + o));
    }
    if (tid < 128) { b1s[tid] = fc1b[tid]; fc2s[tid] = fc2w[tid]; }
    __syncthreads();

    int tm = tid >> 4, tn = tid & 15;
    float acc[8][8];
    #pragma unroll
    for (int i = 0; i < 8; i++)
        #pragma unroll
        for (int j = 0; j < 8; j++) acc[i][j] = 0.0f;
    for (int i = 0; i < 64; i++) {
        float av[8], bv[8];
        #pragma unroll
        for (int ii = 0; ii < 8; ii++) av[ii] = xs[i * 128 + tm * 8 + ii];
        #pragma unroll
        for (int jj = 0; jj < 8; jj++) bv[jj] = fc1s[i * 128 + tn * 8 + jj];
        #pragma unroll
        for (int ii = 0; ii < 8; ii++)
            #pragma unroll
            for (int jj = 0; jj < 8; jj++) acc[ii][jj] += av[ii] * bv[jj];
    }
    float part[8];
    #pragma unroll
    for (int ii = 0; ii < 8; ii++) {
        float p = 0.0f;
        #pragma unroll
        for (int jj = 0; jj < 8; jj++) {
            float h = gelu_f(acc[ii][jj] + b1s[tn * 8 + jj]);
            p += h * fc2s[tn * 8 + jj];
        }
        part[ii] = p;
    }
    __syncthreads();
    float* red = xs;
    #pragma unroll
    for (int ii = 0; ii < 8; ii++) red[(tm * 8 + ii) * 16 + tn] = part[ii];
    __syncthreads();
    if (tid < 128) {
        float ssum = fc2b[0];
        #pragma unroll
        for (int t = 0; t < 16; t++) ssum += red[tid * 16 + t];
        out[(size_t)b * S + s0 + tid] = ssum;
    }
}

// ---------------------------------------------------------------------------
extern "C" void kernel_launch(void* const* d_in, const int* in_sizes, int n_in,
                              void* d_out, int out_size) {
    const float* u    = (const float*)d_in[0];
    const float* fc0w = (const float*)d_in[1];
    const float* fc0b = (const float*)d_in[2];
    const float* swr  = (const float*)d_in[3];
    const float* swi  = (const float*)d_in[4];
    const float* pww  = (const float*)d_in[5];
    const float* pwb  = (const float*)d_in[6];
    const float* fc1w = (const float*)d_in[7];
    const float* fc1b = (const float*)d_in[8];
    const float* fc2w = (const float*)d_in[9];
    const float* fc2b = (const float*)d_in[10];
    float* out = (float*)d_out;

    cudaFuncSetAttribute(mixk,   cudaFuncAttributeMaxDynamicSharedMemorySize, 65536);
    cudaFuncSetAttribute(headk,  cudaFuncAttributeMaxDynamicSharedMemorySize, 66560);
    cudaFuncSetAttribute(tc_fwd, cudaFuncAttributeMaxDynamicSharedMemorySize, 73728);
    cudaFuncSetAttribute(tc_inv, cudaFuncAttributeMaxDynamicSharedMemorySize, 73728);

    __half *pE0h, *pE0l, *pO0h, *pO0l, *pE1h, *pE1l, *pO1h, *pO1l;
    cudaGetSymbolAddress((void**)&pE0h, d_E0h);
    cudaGetSymbolAddress((void**)&pE0l, d_E0l);
    cudaGetSymbolAddress((void**)&pO0h, d_O0h);
    cudaGetSymbolAddress((void**)&pO0l, d_O0l);
    cudaGetSymbolAddress((void**)&pE1h, d_E1h);
    cudaGetSymbolAddress((void**)&pE1l, d_E1l);
    cudaGetSymbolAddress((void**)&pO1h, d_O1h);
    cudaGetSymbolAddress((void**)&pO1l, d_O1l);

    gen_table<<<32, 256>>>();
    gen_basis<<<4096, 256>>>();
    wtrans<<<dim3(8, 512, 2), dim3(32, 32)>>>(swr, swi);
    lift_fold<<<32768, 256>>>(u, fc0w, fc0b, pE0h, pE0l, pO0h, pO0l);

    __half *Eih = pE0h, *Eil = pE0l, *Oih = pO0h, *Oil = pO0l;
    __half *Eoh = pE1h, *Eol = pE1l, *Ooh = pO1h, *Ool = pO1l;
    for (int l = 0; l < 4; l++) {
        tc_fwd<<<dim3(2, 32, 2), 256, 73728>>>(Eih, Eil, Oih, Oil);
        mixk<<<256, 256, 65536>>>(l);
        pwpack<<<1024, 256>>>(pww + l * W * W);
        tc_inv<<<dim3(32, 64), 256, 73728>>>(Eih, Eil, Oih, Oil,
                                             Eoh, Eol, Ooh, Ool,
                                             pwb + l * W, (l < 3) ? 1 : 0);
        __half* t;
        t = Eih; Eih = Eoh; Eoh = t;
        t = Eil; Eil = Eol; Eol = t;
        t = Oih; Oih = Ooh; Ooh = t;
        t = Oil; Oil = Ool; Ool = t;
    }
    headk<<<dim3(64, 64), 256, 66560>>>(Eih, Eil, Oih, Oil,
                                        fc1w, fc1b, fc2w, fc2b, out);
}

// round 16
// speedup vs baseline: 1.3481x; 1.1447x over previous
#include <cuda_runtime.h>
#include <cuda_fp16.h>
#include <math.h>

#define S     8192
#define SMASK 8191
#define HS    4096      // S/2
#define W     64
#define MODES 256
#define RTOT  4096      // 64 batches * 64 channels
#define KA    640       // inv-GEMM A width: (128re+128im+64pw) even + same odd
#define INV_SCALE 0.000244140625f   // 1/4096

// ---------------- scratch (device globals; no allocations) ----------------
__device__ __half d_E0h[RTOT * HS], d_E0l[RTOT * HS];
__device__ __half d_O0h[RTOT * HS], d_O0l[RTOT * HS];
__device__ __half d_E1h[RTOT * HS], d_E1l[RTOT * HS];
__device__ __half d_O1h[RTOT * HS], d_O1l[RTOT * HS];
__device__ __half d_Bf0h[HS * 256], d_Bf0l[HS * 256];   // fwd basis even modes [n][c]
__device__ __half d_Bf1h[HS * 256], d_Bf1l[HS * 256];   // fwd basis odd  modes [n][c]
__device__ __half d_BiSh[256 * HS], d_BiSl[256 * HS];   // inv basis even [c][n]
__device__ __half d_BiDh[256 * HS], d_BiDl[256 * HS];   // inv basis odd  [c][n]
__device__ float  d_CT[512 * RTOT];                     // fwd out, [c][r]
__device__ __half d_Ah[RTOT * KA], d_Al[RTOT * KA];     // inv-GEMM A
__device__ float  d_WTr[4 * 256 * 64 * 64];             // spectral W re [l][k][i][o]
__device__ float  d_WTi[4 * 256 * 64 * 64];             // spectral W im
__device__ float  d_tab[8192];                          // cos table

__device__ __forceinline__ float gelu_f(float x) {
    return 0.5f * x * (1.0f + erff(x * 0.7071067811865476f));
}

// ---------------- PTX helpers ----------------------------------------------
#define CP_ASYNC(dst, src) \
    asm volatile("cp.async.cg.shared.global [%0], [%1], 16;" :: "r"(dst), "l"(src))
#define CP_COMMIT() asm volatile("cp.async.commit_group;")
#define CP_WAIT1()  asm volatile("cp.async.wait_group 1;")
#define CP_WAIT0()  asm volatile("cp.async.wait_group 0;")

__device__ __forceinline__ void ldsm4(unsigned a, unsigned* r) {
    asm volatile("ldmatrix.sync.aligned.m8n8.x4.shared.b16 {%0,%1,%2,%3}, [%4];"
                 : "=r"(r[0]), "=r"(r[1]), "=r"(r[2]), "=r"(r[3]) : "r"(a));
}
__device__ __forceinline__ void ldsm4t(unsigned a, unsigned* r) {
    asm volatile("ldmatrix.sync.aligned.m8n8.x4.trans.shared.b16 {%0,%1,%2,%3}, [%4];"
                 : "=r"(r[0]), "=r"(r[1]), "=r"(r[2]), "=r"(r[3]) : "r"(a));
}
__device__ __forceinline__ void mma16816(float* c, const unsigned* a, const unsigned* b) {
    asm volatile("mma.sync.aligned.m16n8k16.row.col.f32.f16.f16.f32 "
                 "{%0,%1,%2,%3}, {%4,%5,%6,%7}, {%8,%9}, {%0,%1,%2,%3};"
                 : "+f"(c[0]), "+f"(c[1]), "+f"(c[2]), "+f"(c[3])
                 : "r"(a[0]), "r"(a[1]), "r"(a[2]), "r"(a[3]), "r"(b[0]), "r"(b[1]));
}
__device__ __forceinline__ void split_store(float v, __half* ph, __half* pl) {
    __half h = __float2half_rn(v);
    *ph = h;
    *pl = __float2half_rn(v - __half2float(h));
}

// ---------------- basis via cos table ---------------------------------------
__global__ void gen_table() {
    int j = blockIdx.x * 256 + threadIdx.x;
    d_tab[j] = cospif((float)j * (1.0f / 4096.0f));
}
__global__ void gen_basis() {
    int idx = blockIdx.x * 256 + threadIdx.x;   // n*256 + c
    int n = idx >> 8, c = idx & 255, m = c & 127;
    bool sp = (c >= 128);
    #pragma unroll
    for (int par = 0; par < 2; par++) {
        int k = 2 * m + par;
        int j = (k * n) & SMASK;
        float v = sp ? d_tab[(j + 2048) & SMASK] : d_tab[j];   // -sin / cos
        __half h = __float2half_rn(v);
        __half l = __float2half_rn(v - __half2float(h));
        if (par == 0) {
            d_Bf0h[n * 256 + c] = h; d_Bf0l[n * 256 + c] = l;
            d_BiSh[c * HS + n]  = h; d_BiSl[c * HS + n]  = l;
        } else {
            d_Bf1h[n * 256 + c] = h; d_Bf1l[n * 256 + c] = l;
            d_BiDh[c * HS + n]  = h; d_BiDl[c * HS + n]  = l;
        }
    }
}

// ---------------- spectral-weight transpose: [l,i,o,k] -> [l,k,i,o] --------
__global__ void wtrans(const float* __restrict__ swr, const float* __restrict__ swi) {
    __shared__ float t[32][33];
    const float* src = blockIdx.z ? swi : swr;
    float*       dst = blockIdx.z ? d_WTi : d_WTr;
    int k0 = blockIdx.x * 32, R0 = blockIdx.y * 32;
    t[threadIdx.y][threadIdx.x] = src[(R0 + threadIdx.y) * 256 + k0 + threadIdx.x];
    __syncthreads();
    int l = R0 >> 12, io0 = R0 & 4095;
    dst[(l * 256 + k0 + threadIdx.y) * 4096 + io0 + threadIdx.x] = t[threadIdx.x][threadIdx.y];
}

// ---------------- lifting + fold (2 elems/thread, half2 stores) -------------
__global__ void lift_fold(const float* __restrict__ u, const float* __restrict__ fc0w,
                          const float* __restrict__ fc0b,
                          __half* __restrict__ Eh, __half* __restrict__ El,
                          __half* __restrict__ Oh, __half* __restrict__ Ol) {
    int idx = blockIdx.x * 256 + threadIdx.x;   // (b*64+w)*2048 + n/2
    int n = (idx & 2047) * 2;
    int r = idx >> 11;
    int w = r & 63;
    int b = r >> 6;
    float w0 = fc0w[w], w1 = fc0w[64 + w], bb = fc0b[w];
    float2 ua = *(const float2*)&u[(size_t)b * S + n];
    float2 ub = *(const float2*)&u[(size_t)b * S + n + HS];
    const float gi = 1.0f / 8191.0f;
    float lo0 = ua.x * w0 + (float)n * gi * w1 + bb;
    float lo1 = ua.y * w0 + (float)(n + 1) * gi * w1 + bb;
    float hi0 = ub.x * w0 + (float)(n + HS) * gi * w1 + bb;
    float hi1 = ub.y * w0 + (float)(n + HS + 1) * gi * w1 + bb;
    float E0 = lo0 + hi0, E1 = lo1 + hi1;
    float O0 = lo0 - hi0, O1 = lo1 - hi1;
    size_t off = (size_t)r * HS + n;
    __half eh0 = __float2half_rn(E0), eh1 = __float2half_rn(E1);
    __half oh0 = __float2half_rn(O0), oh1 = __float2half_rn(O1);
    *(__half2*)(Eh + off) = __halves2half2(eh0, eh1);
    *(__half2*)(El + off) = __halves2half2(__float2half_rn(E0 - __half2float(eh0)),
                                           __float2half_rn(E1 - __half2float(eh1)));
    *(__half2*)(Oh + off) = __halves2half2(oh0, oh1);
    *(__half2*)(Ol + off) = __halves2half2(__float2half_rn(O0 - __half2float(oh0)),
                                           __float2half_rn(O1 - __half2float(oh1)));
}

// ---------------- forward DFT: tensor-core GEMM ----------------------------
// z=0: even modes from E; z=1: odd modes from O. C[4096x256] = A[4096x4096] @ Bf
// 1-product (Ah x Bh): error confined to the (strongly attenuated) spectral branch.
// Final-iteration wait_group 0 closes the last-stage cp.async race.
__global__ __launch_bounds__(256, 1) void tc_fwd(const __half* __restrict__ Eh,
                                                 const __half* __restrict__ El,
                                                 const __half* __restrict__ Oh,
                                                 const __half* __restrict__ Ol) {
    extern __shared__ __align__(16) char smem[];
    unsigned sbase = (unsigned)__cvta_generic_to_shared(smem);
    const int tid = threadIdx.x, lane = tid & 31, warp = tid >> 5;
    const int bm = blockIdx.y, bn = blockIdx.x, z = blockIdx.z;
    const __half* gAh = (z ? Oh : Eh) + (size_t)bm * 128 * HS;
    const __half* gBh = (z ? d_Bf1h : d_Bf0h) + bn * 128;

    // stage (16KB): Ah 0..8191, Bh 8192..16383
    auto issue = [&](int st, int k0) {
        unsigned s0 = sbase + (unsigned)st * 16384u;
        #pragma unroll
        for (int j = 0; j < 2; j++) {
            int id = tid * 2 + j;
            int r = id >> 2, c = id & 3;                       // A: 128 rows x 4 chunks
            unsigned sa = s0 + r * 64 + ((c ^ ((r >> 1) & 3)) << 4);
            CP_ASYNC(sa, gAh + (size_t)r * HS + k0 + c * 8);
            int k = id >> 4, cc = id & 15;                     // B: 32 rows x 16 chunks
            unsigned sb = s0 + 8192u + k * 256 + ((cc ^ (k & 7)) << 4);
            CP_ASYNC(sb, gBh + (size_t)(k0 + k) * 256 + cc * 8);
        }
        CP_COMMIT();
    };

    float C[2][8][4];
    #pragma unroll
    for (int i = 0; i < 2; i++)
        #pragma unroll
        for (int j = 0; j < 8; j++)
            #pragma unroll
            for (int q = 0; q < 4; q++) C[i][j][q] = 0.0f;

    const int m0w = (warp >> 1) * 32, n0w = (warp & 1) * 64;

    issue(0, 0); issue(1, 32);
    for (int i = 0; i < 128; i++) {
        if (i < 127) { CP_WAIT1(); } else { CP_WAIT0(); }
        __syncthreads();
        if (i + 2 < 128) issue((i + 2) % 3, (i + 2) * 32);
        unsigned s0 = sbase + (unsigned)(i % 3) * 16384u;
        #pragma unroll
        for (int ks = 0; ks < 2; ks++) {
            const int kk = ks * 16;
            unsigned ah[2][4];
            #pragma unroll
            for (int mi = 0; mi < 2; mi++) {
                int r = m0w + mi * 16 + (lane & 15);
                int ch = (kk >> 3) + (lane >> 4);
                unsigned ad = s0 + r * 64 + ((ch ^ ((r >> 1) & 3)) << 4);
                ldsm4(ad, ah[mi]);
            }
            unsigned bh[8][2];
            #pragma unroll
            for (int g = 0; g < 4; g++) {
                int kr = kk + (lane & 7) + ((lane >> 3) & 1) * 8;
                int ch = ((n0w + g * 16) >> 3) + (lane >> 4);
                unsigned ad = s0 + 8192u + kr * 256 + ((ch ^ (kr & 7)) << 4);
                unsigned t[4];
                ldsm4t(ad, t);
                bh[2*g][0] = t[0]; bh[2*g][1] = t[1]; bh[2*g+1][0] = t[2]; bh[2*g+1][1] = t[3];
            }
            #pragma unroll
            for (int mi = 0; mi < 2; mi++)
                #pragma unroll
                for (int nj = 0; nj < 8; nj++)
                    mma16816(C[mi][nj], ah[mi], bh[nj]);
        }
    }
    // store into d_CT with mode remap: local col cl -> mode k=2*cl+z (Re) / Im block
    const int r0 = bm * 128 + m0w + (lane >> 2);
    const int cl0 = bn * 128 + n0w + (lane & 3) * 2;
    #pragma unroll
    for (int mi = 0; mi < 2; mi++)
        #pragma unroll
        for (int nj = 0; nj < 8; nj++) {
            int r = r0 + mi * 16;
            int cl = cl0 + nj * 8;
            int row0 = (cl < 128) ? (2 * cl + z) : (256 + 2 * (cl - 128) + z);
            d_CT[(size_t)row0 * RTOT + r]           = C[mi][nj][0];
            d_CT[(size_t)(row0 + 2) * RTOT + r]     = C[mi][nj][1];
            d_CT[(size_t)row0 * RTOT + r + 8]       = C[mi][nj][2];
            d_CT[(size_t)(row0 + 2) * RTOT + r + 8] = C[mi][nj][3];
        }
}

// ---------------- per-mode complex channel mix -> inv-GEMM A ----------------
__global__ __launch_bounds__(256) void mixk(int l) {
    extern __shared__ float sm[];
    float* Wr = sm;        float* Wi = sm + 4096;
    float* Xr = sm + 8192; float* Xi = sm + 12288;
    int k = blockIdx.x, tid = threadIdx.x;
    const float* wr = d_WTr + (size_t)(l * MODES + k) * 4096;
    const float* wi = d_WTi + (size_t)(l * MODES + k) * 4096;
    const float* cr = d_CT + (size_t)k * RTOT;
    const float* ci = d_CT + (size_t)(MODES + k) * RTOT;
    #pragma unroll
    for (int j = 0; j < 16; j++) {
        int idx = tid + 256 * j;
        Wr[idx] = wr[idx]; Wi[idx] = wi[idx];
        Xr[idx] = cr[idx]; Xi[idx] = ci[idx];
    }
    __syncthreads();
    int o = tid & 63;
    int b0 = tid >> 6;
    float ar[16], ai[16];
    #pragma unroll
    for (int j = 0; j < 16; j++) { ar[j] = 0.0f; ai[j] = 0.0f; }
    for (int i = 0; i < 64; i++) {
        float wre = Wr[i * 64 + o], wim = Wi[i * 64 + o];
        #pragma unroll
        for (int j = 0; j < 16; j++) {
            int b = b0 + 4 * j;
            float xr = Xr[b * 64 + i], xi = Xi[b * 64 + i];
            ar[j] += xr * wre - xi * wim;
            ai[j] += xr * wim + xi * wre;
        }
    }
    int par = k & 1, m = k >> 1;
    float fa = (k == 0) ? 0.5f : 1.0f;
    #pragma unroll
    for (int j = 0; j < 16; j++) {
        int lin = tid + 256 * j;                 // = b*64 + o
        size_t base = (size_t)lin * KA + par * 320;
        split_store(ar[j] * fa, &d_Ah[base + m], &d_Al[base + m]);
        split_store((k == 0) ? 0.0f : ai[j], &d_Ah[base + 128 + m], &d_Al[base + 128 + m]);
    }
}

// ---------------- pack pointwise weights into inv-GEMM A --------------------
__global__ void pwpack(const float* __restrict__ pw) {
    int idx = blockIdx.x * 256 + threadIdx.x;    // b*4096 + o*64 + i
    int i = idx & 63, o = (idx >> 6) & 63, b = idx >> 12;
    float v = pw[o * 64 + i] * 2048.0f;
    size_t base = (size_t)(b * 64 + o) * KA;
    split_store(v, &d_Ah[base + 256 + i], &d_Al[base + 256 + i]);
    split_store(v, &d_Ah[base + 576 + i], &d_Al[base + 576 + i]);
}

// ---------------- fused inverse DFT + pointwise + gelu + refold -------------
// Basis chunks (spectral branch): 1 product AhxBh. Activation chunks: 3 products.
// Final-iteration wait_group 0 closes the last-stage cp.async race.
#define MMABLK3(Cx) \
    _Pragma("unroll") \
    for (int mi = 0; mi < 2; mi++) \
        _Pragma("unroll") \
        for (int nj = 0; nj < 4; nj++) { \
            mma16816(Cx[mi][nj], ah[mi], bh[nj]); \
            mma16816(Cx[mi][nj], ah[mi], bl[nj]); \
            mma16816(Cx[mi][nj], al[mi], bh[nj]); \
        }
#define MMABLK1(Cx) \
    _Pragma("unroll") \
    for (int mi = 0; mi < 2; mi++) \
        _Pragma("unroll") \
        for (int nj = 0; nj < 4; nj++) \
            mma16816(Cx[mi][nj], ah[mi], bh[nj]);

__global__ __launch_bounds__(256, 2) void tc_inv(const __half* __restrict__ Einh,
                                                 const __half* __restrict__ Einl,
                                                 const __half* __restrict__ Oinh,
                                                 const __half* __restrict__ Oinl,
                                                 __half* __restrict__ Eoh,
                                                 __half* __restrict__ Eol,
                                                 __half* __restrict__ Ooh,
                                                 __half* __restrict__ Ool,
                                                 const float* __restrict__ pwb,
                                                 int dogelu) {
    extern __shared__ __align__(16) char smem[];
    unsigned sbase = (unsigned)__cvta_generic_to_shared(smem);
    const int tid = threadIdx.x, lane = tid & 31, warp = tid >> 5;
    const int b = blockIdx.y;
    const int n0 = blockIdx.x * 128;
    const size_t bofs = (size_t)b * 64 * HS;
    const __half* gAh = d_Ah + (size_t)b * 64 * KA;
    const __half* gAl = d_Al + (size_t)b * 64 * KA;

    // stage (24KB): Ah 0..4095, Al 4096..8191, Bh 8192..16383, Bl 16384..24575
    auto issue = [&](int st, int c0) {
        unsigned s0 = sbase + (unsigned)st * 24576u;
        {   int r = tid >> 2, c = tid & 3;          // A: 64 rows x 4 chunks
            unsigned sa = s0 + r * 64 + ((c ^ ((r >> 1) & 3)) << 4);
            size_t ga = (size_t)r * KA + c0 + c * 8;
            CP_ASYNC(sa, gAh + ga);
            CP_ASYNC(sa + 4096u, gAl + ga);
        }
        #pragma unroll
        for (int j = 0; j < 2; j++) {
            int id = tid * 2 + j;
            int k = id >> 4, cc = id & 15;          // B: 32 rows x 16 chunks
            int cg = c0 + k;
            const __half *ph, *pl;
            if (cg < 256)      { size_t o = (size_t)cg * HS + n0 + cc * 8;          ph = d_BiSh + o;       pl = d_BiSl + o; }
            else if (cg < 320) { size_t o = (size_t)(cg - 256) * HS + n0 + cc * 8;  ph = Einh + bofs + o;  pl = Einl + bofs + o; }
            else if (cg < 576) { size_t o = (size_t)(cg - 320) * HS + n0 + cc * 8;  ph = d_BiDh + o;       pl = d_BiDl + o; }
            else               { size_t o = (size_t)(cg - 576) * HS + n0 + cc * 8;  ph = Oinh + bofs + o;  pl = Oinl + bofs + o; }
            unsigned sb = s0 + 8192u + k * 256 + ((cc ^ (k & 7)) << 4);
            CP_ASYNC(sb, ph);
            CP_ASYNC(sb + 8192u, pl);
        }
        CP_COMMIT();
    };

    float Cs[2][4][4], Cd[2][4][4];
    #pragma unroll
    for (int i = 0; i < 2; i++)
        #pragma unroll
        for (int j = 0; j < 4; j++)
            #pragma unroll
            for (int q = 0; q < 4; q++) { Cs[i][j][q] = 0.0f; Cd[i][j][q] = 0.0f; }

    const int m0w = (warp >> 2) * 32, n0w = (warp & 3) * 32;

    issue(0, 0); issue(1, 32);
    for (int i = 0; i < 20; i++) {
        if (i < 19) { CP_WAIT1(); } else { CP_WAIT0(); }
        __syncthreads();
        if (i + 2 < 20) issue((i + 2) % 3, (i + 2) * 32);
        unsigned s0 = sbase + (unsigned)(i % 3) * 24576u;
        const bool act = (i == 8) || (i == 9) || (i == 18) || (i == 19);
        #pragma unroll
        for (int ks = 0; ks < 2; ks++) {
            const int kk = ks * 16;
            unsigned ah[2][4], al[2][4];
            #pragma unroll
            for (int mi = 0; mi < 2; mi++) {
                int r = m0w + mi * 16 + (lane & 15);
                int ch = (kk >> 3) + (lane >> 4);
                unsigned ad = s0 + r * 64 + ((ch ^ ((r >> 1) & 3)) << 4);
                ldsm4(ad, ah[mi]);
                if (act) ldsm4(ad + 4096u, al[mi]);
            }
            unsigned bh[4][2], bl[4][2];
            #pragma unroll
            for (int g = 0; g < 2; g++) {
                int kr = kk + (lane & 7) + ((lane >> 3) & 1) * 8;
                int ch = ((n0w + g * 16) >> 3) + (lane >> 4);
                unsigned ad = s0 + 8192u + kr * 256 + ((ch ^ (kr & 7)) << 4);
                unsigned t[4];
                ldsm4t(ad, t);
                bh[2*g][0] = t[0]; bh[2*g][1] = t[1]; bh[2*g+1][0] = t[2]; bh[2*g+1][1] = t[3];
                if (act) {
                    ldsm4t(ad + 8192u, t);
                    bl[2*g][0] = t[0]; bl[2*g][1] = t[1]; bl[2*g+1][0] = t[2]; bl[2*g+1][1] = t[3];
                }
            }
            if (i < 10) {
                if (act) { MMABLK3(Cs) } else { MMABLK1(Cs) }
            } else {
                if (act) { MMABLK3(Cd) } else { MMABLK1(Cd) }
            }
        }
    }
    // epilogue
    const int o0 = m0w + (lane >> 2);
    const int nl0 = n0w + (lane & 3) * 2;
    #pragma unroll
    for (int mi = 0; mi < 2; mi++)
        #pragma unroll
        for (int h = 0; h < 2; h++) {
            int o = o0 + mi * 16 + h * 8;
            float bias = pwb[o];
            size_t rowo = ((size_t)(b * 64 + o)) * HS;
            #pragma unroll
            for (int nj = 0; nj < 4; nj++) {
                int ng = n0 + nl0 + nj * 8;
                float s0v = Cs[mi][nj][h * 2],     d0v = Cd[mi][nj][h * 2];
                float s1v = Cs[mi][nj][h * 2 + 1], d1v = Cd[mi][nj][h * 2 + 1];
                float ylo0 = (s0v + d0v) * INV_SCALE + bias;
                float yhi0 = (s0v - d0v) * INV_SCALE + bias;
                float ylo1 = (s1v + d1v) * INV_SCALE + bias;
                float yhi1 = (s1v - d1v) * INV_SCALE + bias;
                if (dogelu) {
                    ylo0 = gelu_f(ylo0); yhi0 = gelu_f(yhi0);
                    ylo1 = gelu_f(ylo1); yhi1 = gelu_f(yhi1);
                }
                float E0 = ylo0 + yhi0, O0 = ylo0 - yhi0;
                float E1 = ylo1 + yhi1, O1 = ylo1 - yhi1;
                __half eh0 = __float2half_rn(E0), eh1 = __float2half_rn(E1);
                __half el0 = __float2half_rn(E0 - __half2float(eh0));
                __half el1 = __float2half_rn(E1 - __half2float(eh1));
                __half oh0 = __float2half_rn(O0), oh1 = __float2half_rn(O1);
                __half ol0 = __float2half_rn(O0 - __half2float(oh0));
                __half ol1 = __float2half_rn(O1 - __half2float(oh1));
                *(__half2*)(Eoh + rowo + ng) = __halves2half2(eh0, eh1);
                *(__half2*)(Eol + rowo + ng) = __halves2half2(el0, el1);
                *(__half2*)(Ooh + rowo + ng) = __halves2half2(oh0, oh1);
                *(__half2*)(Ool + rowo + ng) = __halves2half2(ol0, ol1);
            }
        }
}

// ---------------- head: gelu(x^T @ fc1 + b1) @ fc2 + b2 --------------------
__global__ __launch_bounds__(256) void headk(const __half* __restrict__ Eh,
                                             const __half* __restrict__ El,
                                             const __half* __restrict__ Oh,
                                             const __half* __restrict__ Ol,
                                             const float* __restrict__ fc1w,
                                             const float* __restrict__ fc1b,
                                             const float* __restrict__ fc2w,
                                             const float* __restrict__ fc2b,
                                             float* __restrict__ out) {
    extern __shared__ float sm[];
    float* fc1s = sm;            // [64][128]
    float* xs   = sm + 8192;     // [64][128], reused for reduction
    float* b1s  = sm + 16384;    // [128]
    float* fc2s = sm + 16512;    // [128]
    int b = blockIdx.y;
    int s0 = blockIdx.x * 128;
    int tid = threadIdx.x;
    int hi = (s0 >= HS);
    int sh = s0 & (HS - 1);
    #pragma unroll
    for (int j = 0; j < 32; j++) {
        int idx = tid + 256 * j;
        fc1s[idx] = fc1w[idx];
        size_t off = (size_t)(b * 64 + (idx >> 7)) * HS + sh + (idx & 127);
        float e = __half2float(Eh[off]) + __half2float(El[off]);
        float o = __half2float(Oh[off]) + __half2float(Ol[off]);
        xs[idx] = 0.5f * (hi ? (e - o) : (e + o));
    }
    if (tid < 128) { b1s[tid] = fc1b[tid]; fc2s[tid] = fc2w[tid]; }
    __syncthreads();

    int tm = tid >> 4, tn = tid & 15;
    float acc[8][8];
    #pragma unroll
    for (int i = 0; i < 8; i++)
        #pragma unroll
        for (int j = 0; j < 8; j++) acc[i][j] = 0.0f;
    for (int i = 0; i < 64; i++) {
        float av[8], bv[8];
        #pragma unroll
        for (int ii = 0; ii < 8; ii++) av[ii] = xs[i * 128 + tm * 8 + ii];
        #pragma unroll
        for (int jj = 0; jj < 8; jj++) bv[jj] = fc1s[i * 128 + tn * 8 + jj];
        #pragma unroll
        for (int ii = 0; ii < 8; ii++)
            #pragma unroll
            for (int jj = 0; jj < 8; jj++) acc[ii][jj] += av[ii] * bv[jj];
    }
    float part[8];
    #pragma unroll
    for (int ii = 0; ii < 8; ii++) {
        float p = 0.0f;
        #pragma unroll
        for (int jj = 0; jj < 8; jj++) {
            float h = gelu_f(acc[ii][jj] + b1s[tn * 8 + jj]);
            p += h * fc2s[tn * 8 + jj];
        }
        part[ii] = p;
    }
    __syncthreads();
    float* red = xs;
    #pragma unroll
    for (int ii = 0; ii < 8; ii++) red[(tm * 8 + ii) * 16 + tn] = part[ii];
    __syncthreads();
    if (tid < 128) {
        float ssum = fc2b[0];
        #pragma unroll
        for (int t = 0; t < 16; t++) ssum += red[tid * 16 + t];
        out[(size_t)b * S + s0 + tid] = ssum;
    }
}

// ---------------------------------------------------------------------------
extern "C" void kernel_launch(void* const* d_in, const int* in_sizes, int n_in,
                              void* d_out, int out_size) {
    const float* u    = (const float*)d_in[0];
    const float* fc0w = (const float*)d_in[1];
    const float* fc0b = (const float*)d_in[2];
    const float* swr  = (const float*)d_in[3];
    const float* swi  = (const float*)d_in[4];
    const float* pww  = (const float*)d_in[5];
    const float* pwb  = (const float*)d_in[6];
    const float* fc1w = (const float*)d_in[7];
    const float* fc1b = (const float*)d_in[8];
    const float* fc2w = (const float*)d_in[9];
    const float* fc2b = (const float*)d_in[10];
    float* out = (float*)d_out;

    cudaFuncSetAttribute(mixk,   cudaFuncAttributeMaxDynamicSharedMemorySize, 65536);
    cudaFuncSetAttribute(headk,  cudaFuncAttributeMaxDynamicSharedMemorySize, 66560);
    cudaFuncSetAttribute(tc_fwd, cudaFuncAttributeMaxDynamicSharedMemorySize, 49152);
    cudaFuncSetAttribute(tc_inv, cudaFuncAttributeMaxDynamicSharedMemorySize, 73728);

    __half *pE0h, *pE0l, *pO0h, *pO0l, *pE1h, *pE1l, *pO1h, *pO1l;
    cudaGetSymbolAddress((void**)&pE0h, d_E0h);
    cudaGetSymbolAddress((void**)&pE0l, d_E0l);
    cudaGetSymbolAddress((void**)&pO0h, d_O0h);
    cudaGetSymbolAddress((void**)&pO0l, d_O0l);
    cudaGetSymbolAddress((void**)&pE1h, d_E1h);
    cudaGetSymbolAddress((void**)&pE1l, d_E1l);
    cudaGetSymbolAddress((void**)&pO1h, d_O1h);
    cudaGetSymbolAddress((void**)&pO1l, d_O1l);

    gen_table<<<32, 256>>>();
    gen_basis<<<4096, 256>>>();
    wtrans<<<dim3(8, 512, 2), dim3(32, 32)>>>(swr, swi);
    lift_fold<<<32768, 256>>>(u, fc0w, fc0b, pE0h, pE0l, pO0h, pO0l);

    __half *Eih = pE0h, *Eil = pE0l, *Oih = pO0h, *Oil = pO0l;
    __half *Eoh = pE1h, *Eol = pE1l, *Ooh = pO1h, *Ool = pO1l;
    for (int l = 0; l < 4; l++) {
        tc_fwd<<<dim3(2, 32, 2), 256, 49152>>>(Eih, Eil, Oih, Oil);
        mixk<<<256, 256, 65536>>>(l);
        pwpack<<<1024, 256>>>(pww + l * W * W);
        tc_inv<<<dim3(32, 64), 256, 73728>>>(Eih, Eil, Oih, Oil,
                                             Eoh, Eol, Ooh, Ool,
                                             pwb + l * W, (l < 3) ? 1 : 0);
        __half* t;
        t = Eih; Eih = Eoh; Eoh = t;
        t = Eil; Eil = Eol; Eol = t;
        t = Oih; Oih = Ooh; Ooh = t;
        t = Oil; Oil = Ool; Ool = t;
    }
    headk<<<dim3(64, 64), 256, 66560>>>(Eih, Eil, Oih, Oil,
                                        fc1w, fc1b, fc2w, fc2b, out);
}

// round 17
// speedup vs baseline: 1.3737x; 1.0189x over previous
#include <cuda_runtime.h>
#include <cuda_fp16.h>
#include <math.h>

#define S     8192
#define SMASK 8191
#define HS    4096      // S/2
#define W     64
#define MODES 256
#define RTOT  4096      // 64 batches * 64 channels
#define KA    640       // inv-GEMM A width: (128re+128im+64pw) even + same odd
#define INV_SCALE 0.000244140625f   // 1/4096

// ---------------- scratch (device globals; no allocations) ----------------
__device__ __half d_E0h[RTOT * HS], d_E0l[RTOT * HS];
__device__ __half d_O0h[RTOT * HS], d_O0l[RTOT * HS];
__device__ __half d_E1h[RTOT * HS], d_E1l[RTOT * HS];
__device__ __half d_O1h[RTOT * HS], d_O1l[RTOT * HS];
__device__ __half d_Bf0h[HS * 256], d_Bf0l[HS * 256];   // fwd basis even modes [n][c]
__device__ __half d_Bf1h[HS * 256], d_Bf1l[HS * 256];   // fwd basis odd  modes [n][c]
__device__ __half d_BiSh[256 * HS], d_BiSl[256 * HS];   // inv basis even [c][n]
__device__ __half d_BiDh[256 * HS], d_BiDl[256 * HS];   // inv basis odd  [c][n]
__device__ float  d_CT[512 * RTOT];                     // fwd out, [c][r]
__device__ __half d_Ah[RTOT * KA], d_Al[RTOT * KA];     // inv-GEMM A
__device__ float  d_WTr[4 * 256 * 64 * 64];             // spectral W re [l][k][i][o]
__device__ float  d_WTi[4 * 256 * 64 * 64];             // spectral W im
__device__ float  d_tab[8192];                          // cos table

__device__ __forceinline__ float gelu_f(float x) {
    return 0.5f * x * (1.0f + erff(x * 0.7071067811865476f));
}

// ---------------- PTX helpers ----------------------------------------------
#define CP_ASYNC(dst, src) \
    asm volatile("cp.async.cg.shared.global [%0], [%1], 16;" :: "r"(dst), "l"(src))
#define CP_COMMIT() asm volatile("cp.async.commit_group;")
#define CP_WAIT1()  asm volatile("cp.async.wait_group 1;")
#define CP_WAIT0()  asm volatile("cp.async.wait_group 0;")

__device__ __forceinline__ void ldsm4(unsigned a, unsigned* r) {
    asm volatile("ldmatrix.sync.aligned.m8n8.x4.shared.b16 {%0,%1,%2,%3}, [%4];"
                 : "=r"(r[0]), "=r"(r[1]), "=r"(r[2]), "=r"(r[3]) : "r"(a));
}
__device__ __forceinline__ void ldsm4t(unsigned a, unsigned* r) {
    asm volatile("ldmatrix.sync.aligned.m8n8.x4.trans.shared.b16 {%0,%1,%2,%3}, [%4];"
                 : "=r"(r[0]), "=r"(r[1]), "=r"(r[2]), "=r"(r[3]) : "r"(a));
}
__device__ __forceinline__ void mma16816(float* c, const unsigned* a, const unsigned* b) {
    asm volatile("mma.sync.aligned.m16n8k16.row.col.f32.f16.f16.f32 "
                 "{%0,%1,%2,%3}, {%4,%5,%6,%7}, {%8,%9}, {%0,%1,%2,%3};"
                 : "+f"(c[0]), "+f"(c[1]), "+f"(c[2]), "+f"(c[3])
                 : "r"(a[0]), "r"(a[1]), "r"(a[2]), "r"(a[3]), "r"(b[0]), "r"(b[1]));
}
__device__ __forceinline__ void split_store(float v, __half* ph, __half* pl) {
    __half h = __float2half_rn(v);
    *ph = h;
    *pl = __float2half_rn(v - __half2float(h));
}

// ---------------- basis via cos table ---------------------------------------
__global__ void gen_table() {
    int j = blockIdx.x * 256 + threadIdx.x;
    d_tab[j] = cospif((float)j * (1.0f / 4096.0f));
}
__global__ void gen_basis() {
    int idx = blockIdx.x * 256 + threadIdx.x;   // n*256 + c
    int n = idx >> 8, c = idx & 255, m = c & 127;
    bool sp = (c >= 128);
    #pragma unroll
    for (int par = 0; par < 2; par++) {
        int k = 2 * m + par;
        int j = (k * n) & SMASK;
        float v = sp ? d_tab[(j + 2048) & SMASK] : d_tab[j];   // -sin / cos
        __half h = __float2half_rn(v);
        __half l = __float2half_rn(v - __half2float(h));
        if (par == 0) {
            d_Bf0h[n * 256 + c] = h; d_Bf0l[n * 256 + c] = l;
            d_BiSh[c * HS + n]  = h; d_BiSl[c * HS + n]  = l;
        } else {
            d_Bf1h[n * 256 + c] = h; d_Bf1l[n * 256 + c] = l;
            d_BiDh[c * HS + n]  = h; d_BiDl[c * HS + n]  = l;
        }
    }
}

// ---------------- spectral-weight transpose: [l,i,o,k] -> [l,k,i,o] --------
__global__ void wtrans(const float* __restrict__ swr, const float* __restrict__ swi) {
    __shared__ float t[32][33];
    const float* src = blockIdx.z ? swi : swr;
    float*       dst = blockIdx.z ? d_WTi : d_WTr;
    int k0 = blockIdx.x * 32, R0 = blockIdx.y * 32;
    t[threadIdx.y][threadIdx.x] = src[(R0 + threadIdx.y) * 256 + k0 + threadIdx.x];
    __syncthreads();
    int l = R0 >> 12, io0 = R0 & 4095;
    dst[(l * 256 + k0 + threadIdx.y) * 4096 + io0 + threadIdx.x] = t[threadIdx.x][threadIdx.y];
}

// ---------------- lifting + fold (2 elems/thread, half2 stores) -------------
__global__ void lift_fold(const float* __restrict__ u, const float* __restrict__ fc0w,
                          const float* __restrict__ fc0b,
                          __half* __restrict__ Eh, __half* __restrict__ El,
                          __half* __restrict__ Oh, __half* __restrict__ Ol) {
    int idx = blockIdx.x * 256 + threadIdx.x;   // (b*64+w)*2048 + n/2
    int n = (idx & 2047) * 2;
    int r = idx >> 11;
    int w = r & 63;
    int b = r >> 6;
    float w0 = fc0w[w], w1 = fc0w[64 + w], bb = fc0b[w];
    float2 ua = *(const float2*)&u[(size_t)b * S + n];
    float2 ub = *(const float2*)&u[(size_t)b * S + n + HS];
    const float gi = 1.0f / 8191.0f;
    float lo0 = ua.x * w0 + (float)n * gi * w1 + bb;
    float lo1 = ua.y * w0 + (float)(n + 1) * gi * w1 + bb;
    float hi0 = ub.x * w0 + (float)(n + HS) * gi * w1 + bb;
    float hi1 = ub.y * w0 + (float)(n + HS + 1) * gi * w1 + bb;
    float E0 = lo0 + hi0, E1 = lo1 + hi1;
    float O0 = lo0 - hi0, O1 = lo1 - hi1;
    size_t off = (size_t)r * HS + n;
    __half eh0 = __float2half_rn(E0), eh1 = __float2half_rn(E1);
    __half oh0 = __float2half_rn(O0), oh1 = __float2half_rn(O1);
    *(__half2*)(Eh + off) = __halves2half2(eh0, eh1);
    *(__half2*)(El + off) = __halves2half2(__float2half_rn(E0 - __half2float(eh0)),
                                           __float2half_rn(E1 - __half2float(eh1)));
    *(__half2*)(Oh + off) = __halves2half2(oh0, oh1);
    *(__half2*)(Ol + off) = __halves2half2(__float2half_rn(O0 - __half2float(oh0)),
                                           __float2half_rn(O1 - __half2float(oh1)));
}

// ---------------- forward DFT: tensor-core GEMM ----------------------------
// z=0: even modes from E; z=1: odd modes from O. C[4096x256] = A[4096x4096] @ Bf
// 1-product (Ah x Bh). Final-iteration wait_group 0 closes the cp.async race.
__global__ __launch_bounds__(256, 1) void tc_fwd(const __half* __restrict__ Eh,
                                                 const __half* __restrict__ El,
                                                 const __half* __restrict__ Oh,
                                                 const __half* __restrict__ Ol) {
    extern __shared__ __align__(16) char smem[];
    unsigned sbase = (unsigned)__cvta_generic_to_shared(smem);
    const int tid = threadIdx.x, lane = tid & 31, warp = tid >> 5;
    const int bm = blockIdx.y, bn = blockIdx.x, z = blockIdx.z;
    const __half* gAh = (z ? Oh : Eh) + (size_t)bm * 128 * HS;
    const __half* gBh = (z ? d_Bf1h : d_Bf0h) + bn * 128;

    // stage (16KB): Ah 0..8191, Bh 8192..16383
    auto issue = [&](int st, int k0) {
        unsigned s0 = sbase + (unsigned)st * 16384u;
        #pragma unroll
        for (int j = 0; j < 2; j++) {
            int id = tid * 2 + j;
            int r = id >> 2, c = id & 3;                       // A: 128 rows x 4 chunks
            unsigned sa = s0 + r * 64 + ((c ^ ((r >> 1) & 3)) << 4);
            CP_ASYNC(sa, gAh + (size_t)r * HS + k0 + c * 8);
            int k = id >> 4, cc = id & 15;                     // B: 32 rows x 16 chunks
            unsigned sb = s0 + 8192u + k * 256 + ((cc ^ (k & 7)) << 4);
            CP_ASYNC(sb, gBh + (size_t)(k0 + k) * 256 + cc * 8);
        }
        CP_COMMIT();
    };

    float C[2][8][4];
    #pragma unroll
    for (int i = 0; i < 2; i++)
        #pragma unroll
        for (int j = 0; j < 8; j++)
            #pragma unroll
            for (int q = 0; q < 4; q++) C[i][j][q] = 0.0f;

    const int m0w = (warp >> 1) * 32, n0w = (warp & 1) * 64;

    issue(0, 0); issue(1, 32);
    for (int i = 0; i < 128; i++) {
        if (i < 127) { CP_WAIT1(); } else { CP_WAIT0(); }
        __syncthreads();
        if (i + 2 < 128) issue((i + 2) % 3, (i + 2) * 32);
        unsigned s0 = sbase + (unsigned)(i % 3) * 16384u;
        #pragma unroll
        for (int ks = 0; ks < 2; ks++) {
            const int kk = ks * 16;
            unsigned ah[2][4];
            #pragma unroll
            for (int mi = 0; mi < 2; mi++) {
                int r = m0w + mi * 16 + (lane & 15);
                int ch = (kk >> 3) + (lane >> 4);
                unsigned ad = s0 + r * 64 + ((ch ^ ((r >> 1) & 3)) << 4);
                ldsm4(ad, ah[mi]);
            }
            unsigned bh[8][2];
            #pragma unroll
            for (int g = 0; g < 4; g++) {
                int kr = kk + (lane & 7) + ((lane >> 3) & 1) * 8;
                int ch = ((n0w + g * 16) >> 3) + (lane >> 4);
                unsigned ad = s0 + 8192u + kr * 256 + ((ch ^ (kr & 7)) << 4);
                unsigned t[4];
                ldsm4t(ad, t);
                bh[2*g][0] = t[0]; bh[2*g][1] = t[1]; bh[2*g+1][0] = t[2]; bh[2*g+1][1] = t[3];
            }
            #pragma unroll
            for (int mi = 0; mi < 2; mi++)
                #pragma unroll
                for (int nj = 0; nj < 8; nj++)
                    mma16816(C[mi][nj], ah[mi], bh[nj]);
        }
    }
    // store into d_CT with mode remap: local col cl -> mode k=2*cl+z (Re) / Im block
    const int r0 = bm * 128 + m0w + (lane >> 2);
    const int cl0 = bn * 128 + n0w + (lane & 3) * 2;
    #pragma unroll
    for (int mi = 0; mi < 2; mi++)
        #pragma unroll
        for (int nj = 0; nj < 8; nj++) {
            int r = r0 + mi * 16;
            int cl = cl0 + nj * 8;
            int row0 = (cl < 128) ? (2 * cl + z) : (256 + 2 * (cl - 128) + z);
            d_CT[(size_t)row0 * RTOT + r]           = C[mi][nj][0];
            d_CT[(size_t)(row0 + 2) * RTOT + r]     = C[mi][nj][1];
            d_CT[(size_t)row0 * RTOT + r + 8]       = C[mi][nj][2];
            d_CT[(size_t)(row0 + 2) * RTOT + r + 8] = C[mi][nj][3];
        }
}

// ---------------- per-mode complex channel mix -> inv-GEMM A ----------------
// float4-transposed X tiles (R6-verified inner loop, no split-K).
__global__ __launch_bounds__(256) void mixk(int l) {
    extern __shared__ float sm[];
    float* Wr  = sm;            // 4096
    float* Wi  = sm + 4096;     // 4096
    float* XrT = sm + 8192;     // 64*68, layout [i][b] stride 68
    float* XiT = sm + 12544;    // 4352
    int k = blockIdx.x, tid = threadIdx.x;
    const float* wr = d_WTr + (size_t)(l * MODES + k) * 4096;
    const float* wi = d_WTi + (size_t)(l * MODES + k) * 4096;
    const float* cr = d_CT + (size_t)k * RTOT;
    const float* ci = d_CT + (size_t)(MODES + k) * RTOT;
    #pragma unroll
    for (int j = 0; j < 16; j++) {
        int idx = tid + 256 * j;
        Wr[idx] = wr[idx]; Wi[idx] = wi[idx];
        int i = idx & 63, b = idx >> 6;
        XrT[i * 68 + b] = cr[idx];
        XiT[i * 68 + b] = ci[idx];
    }
    __syncthreads();
    int o = tid & 63;
    int bb = (tid >> 6) * 16;
    float ar[16], ai[16];
    #pragma unroll
    for (int j = 0; j < 16; j++) { ar[j] = 0.0f; ai[j] = 0.0f; }
    for (int i = 0; i < 64; i++) {
        float wre = Wr[i * 64 + o], wim = Wi[i * 64 + o];
        const float4* xr4 = (const float4*)&XrT[i * 68 + bb];
        const float4* xi4 = (const float4*)&XiT[i * 68 + bb];
        #pragma unroll
        for (int q = 0; q < 4; q++) {
            float4 xr = xr4[q], xi = xi4[q];
            float xrv[4] = {xr.x, xr.y, xr.z, xr.w};
            float xiv[4] = {xi.x, xi.y, xi.z, xi.w};
            #pragma unroll
            for (int e = 0; e < 4; e++) {
                int j = q * 4 + e;
                ar[j] += xrv[e] * wre - xiv[e] * wim;
                ai[j] += xrv[e] * wim + xiv[e] * wre;
            }
        }
    }
    int par = k & 1, m = k >> 1;
    float fa = (k == 0) ? 0.5f : 1.0f;
    #pragma unroll
    for (int j = 0; j < 16; j++) {
        int lin = (bb + j) * 64 + o;
        size_t base = (size_t)lin * KA + par * 320;
        split_store(ar[j] * fa, &d_Ah[base + m], &d_Al[base + m]);
        split_store((k == 0) ? 0.0f : ai[j], &d_Ah[base + 128 + m], &d_Al[base + 128 + m]);
    }
}

// ---------------- pack pointwise weights into inv-GEMM A --------------------
__global__ void pwpack(const float* __restrict__ pw) {
    int idx = blockIdx.x * 256 + threadIdx.x;    // b*4096 + o*64 + i
    int i = idx & 63, o = (idx >> 6) & 63, b = idx >> 12;
    float v = pw[o * 64 + i] * 2048.0f;
    size_t base = (size_t)(b * 64 + o) * KA;
    split_store(v, &d_Ah[base + 256 + i], &d_Al[base + 256 + i]);
    split_store(v, &d_Ah[base + 576 + i], &d_Al[base + 576 + i]);
}

// ---------------- fused inverse DFT + pointwise + gelu + refold -------------
// Basis chunks (spectral branch): 1 product AhxBh — lo operands neither loaded
// nor copied. Activation chunks: 3 products. Final-iter wait_group 0.
#define MMABLK3(Cx) \
    _Pragma("unroll") \
    for (int mi = 0; mi < 2; mi++) \
        _Pragma("unroll") \
        for (int nj = 0; nj < 4; nj++) { \
            mma16816(Cx[mi][nj], ah[mi], bh[nj]); \
            mma16816(Cx[mi][nj], ah[mi], bl[nj]); \
            mma16816(Cx[mi][nj], al[mi], bh[nj]); \
        }
#define MMABLK1(Cx) \
    _Pragma("unroll") \
    for (int mi = 0; mi < 2; mi++) \
        _Pragma("unroll") \
        for (int nj = 0; nj < 4; nj++) \
            mma16816(Cx[mi][nj], ah[mi], bh[nj]);

__global__ __launch_bounds__(256, 2) void tc_inv(const __half* __restrict__ Einh,
                                                 const __half* __restrict__ Einl,
                                                 const __half* __restrict__ Oinh,
                                                 const __half* __restrict__ Oinl,
                                                 __half* __restrict__ Eoh,
                                                 __half* __restrict__ Eol,
                                                 __half* __restrict__ Ooh,
                                                 __half* __restrict__ Ool,
                                                 const float* __restrict__ pwb,
                                                 int dogelu) {
    extern __shared__ __align__(16) char smem[];
    unsigned sbase = (unsigned)__cvta_generic_to_shared(smem);
    const int tid = threadIdx.x, lane = tid & 31, warp = tid >> 5;
    const int b = blockIdx.y;
    const int n0 = blockIdx.x * 128;
    const size_t bofs = (size_t)b * 64 * HS;
    const __half* gAh = d_Ah + (size_t)b * 64 * KA;
    const __half* gAl = d_Al + (size_t)b * 64 * KA;

    // stage (24KB): Ah 0..4095, Al 4096..8191, Bh 8192..16383, Bl 16384..24575
    auto issue = [&](int st, int c0) {
        unsigned s0 = sbase + (unsigned)st * 24576u;
        const bool actc = (c0 >= 256 && c0 < 320) || (c0 >= 576);
        {   int r = tid >> 2, c = tid & 3;          // A: 64 rows x 4 chunks
            unsigned sa = s0 + r * 64 + ((c ^ ((r >> 1) & 3)) << 4);
            size_t ga = (size_t)r * KA + c0 + c * 8;
            CP_ASYNC(sa, gAh + ga);
            if (actc) CP_ASYNC(sa + 4096u, gAl + ga);
        }
        #pragma unroll
        for (int j = 0; j < 2; j++) {
            int id = tid * 2 + j;
            int k = id >> 4, cc = id & 15;          // B: 32 rows x 16 chunks
            int cg = c0 + k;
            const __half *ph, *pl;
            if (cg < 256)      { size_t o = (size_t)cg * HS + n0 + cc * 8;          ph = d_BiSh + o;       pl = d_BiSl + o; }
            else if (cg < 320) { size_t o = (size_t)(cg - 256) * HS + n0 + cc * 8;  ph = Einh + bofs + o;  pl = Einl + bofs + o; }
            else if (cg < 576) { size_t o = (size_t)(cg - 320) * HS + n0 + cc * 8;  ph = d_BiDh + o;       pl = d_BiDl + o; }
            else               { size_t o = (size_t)(cg - 576) * HS + n0 + cc * 8;  ph = Oinh + bofs + o;  pl = Oinl + bofs + o; }
            unsigned sb = s0 + 8192u + k * 256 + ((cc ^ (k & 7)) << 4);
            CP_ASYNC(sb, ph);
            if (actc) CP_ASYNC(sb + 8192u, pl);
        }
        CP_COMMIT();
    };

    float Cs[2][4][4], Cd[2][4][4];
    #pragma unroll
    for (int i = 0; i < 2; i++)
        #pragma unroll
        for (int j = 0; j < 4; j++)
            #pragma unroll
            for (int q = 0; q < 4; q++) { Cs[i][j][q] = 0.0f; Cd[i][j][q] = 0.0f; }

    const int m0w = (warp >> 2) * 32, n0w = (warp & 3) * 32;

    issue(0, 0); issue(1, 32);
    for (int i = 0; i < 20; i++) {
        if (i < 19) { CP_WAIT1(); } else { CP_WAIT0(); }
        __syncthreads();
        if (i + 2 < 20) issue((i + 2) % 3, (i + 2) * 32);
        unsigned s0 = sbase + (unsigned)(i % 3) * 24576u;
        const bool act = (i == 8) || (i == 9) || (i == 18) || (i == 19);
        #pragma unroll
        for (int ks = 0; ks < 2; ks++) {
            const int kk = ks * 16;
            unsigned ah[2][4], al[2][4];
            #pragma unroll
            for (int mi = 0; mi < 2; mi++) {
                int r = m0w + mi * 16 + (lane & 15);
                int ch = (kk >> 3) + (lane >> 4);
                unsigned ad = s0 + r * 64 + ((ch ^ ((r >> 1) & 3)) << 4);
                ldsm4(ad, ah[mi]);
                if (act) ldsm4(ad + 4096u, al[mi]);
            }
            unsigned bh[4][2], bl[4][2];
            #pragma unroll
            for (int g = 0; g < 2; g++) {
                int kr = kk + (lane & 7) + ((lane >> 3) & 1) * 8;
                int ch = ((n0w + g * 16) >> 3) + (lane >> 4);
                unsigned ad = s0 + 8192u + kr * 256 + ((ch ^ (kr & 7)) << 4);
                unsigned t[4];
                ldsm4t(ad, t);
                bh[2*g][0] = t[0]; bh[2*g][1] = t[1]; bh[2*g+1][0] = t[2]; bh[2*g+1][1] = t[3];
                if (act) {
                    ldsm4t(ad + 8192u, t);
                    bl[2*g][0] = t[0]; bl[2*g][1] = t[1]; bl[2*g+1][0] = t[2]; bl[2*g+1][1] = t[3];
                }
            }
            if (i < 10) {
                if (act) { MMABLK3(Cs) } else { MMABLK1(Cs) }
            } else {
                if (act) { MMABLK3(Cd) } else { MMABLK1(Cd) }
            }
        }
    }
    // epilogue
    const int o0 = m0w + (lane >> 2);
    const int nl0 = n0w + (lane & 3) * 2;
    #pragma unroll
    for (int mi = 0; mi < 2; mi++)
        #pragma unroll
        for (int h = 0; h < 2; h++) {
            int o = o0 + mi * 16 + h * 8;
            float bias = pwb[o];
            size_t rowo = ((size_t)(b * 64 + o)) * HS;
            #pragma unroll
            for (int nj = 0; nj < 4; nj++) {
                int ng = n0 + nl0 + nj * 8;
                float s0v = Cs[mi][nj][h * 2],     d0v = Cd[mi][nj][h * 2];
                float s1v = Cs[mi][nj][h * 2 + 1], d1v = Cd[mi][nj][h * 2 + 1];
                float ylo0 = (s0v + d0v) * INV_SCALE + bias;
                float yhi0 = (s0v - d0v) * INV_SCALE + bias;
                float ylo1 = (s1v + d1v) * INV_SCALE + bias;
                float yhi1 = (s1v - d1v) * INV_SCALE + bias;
                if (dogelu) {
                    ylo0 = gelu_f(ylo0); yhi0 = gelu_f(yhi0);
                    ylo1 = gelu_f(ylo1); yhi1 = gelu_f(yhi1);
                }
                float E0 = ylo0 + yhi0, O0 = ylo0 - yhi0;
                float E1 = ylo1 + yhi1, O1 = ylo1 - yhi1;
                __half eh0 = __float2half_rn(E0), eh1 = __float2half_rn(E1);
                __half el0 = __float2half_rn(E0 - __half2float(eh0));
                __half el1 = __float2half_rn(E1 - __half2float(eh1));
                __half oh0 = __float2half_rn(O0), oh1 = __float2half_rn(O1);
                __half ol0 = __float2half_rn(O0 - __half2float(oh0));
                __half ol1 = __float2half_rn(O1 - __half2float(oh1));
                *(__half2*)(Eoh + rowo + ng) = __halves2half2(eh0, eh1);
                *(__half2*)(Eol + rowo + ng) = __halves2half2(el0, el1);
                *(__half2*)(Ooh + rowo + ng) = __halves2half2(oh0, oh1);
                *(__half2*)(Ool + rowo + ng) = __halves2half2(ol0, ol1);
            }
        }
}

// ---------------- head: gelu(x^T @ fc1 + b1) @ fc2 + b2 --------------------
__global__ __launch_bounds__(256) void headk(const __half* __restrict__ Eh,
                                             const __half* __restrict__ El,
                                             const __half* __restrict__ Oh,
                                             const __half* __restrict__ Ol,
                                             const float* __restrict__ fc1w,
                                             const float* __restrict__ fc1b,
                                             const float* __restrict__ fc2w,
                                             const float* __restrict__ fc2b,
                                             float* __restrict__ out) {
    extern __shared__ float sm[];
    float* fc1s = sm;            // [64][128]
    float* xs   = sm + 8192;     // [64][128], reused for reduction
    float* b1s  = sm + 16384;    // [128]
    float* fc2s = sm + 16512;    // [128]
    int b = blockIdx.y;
    int s0 = blockIdx.x * 128;
    int tid = threadIdx.x;
    int hi = (s0 >= HS);
    int sh = s0 & (HS - 1);
    #pragma unroll
    for (int j = 0; j < 32; j++) {
        int idx = tid + 256 * j;
        fc1s[idx] = fc1w[idx];
        size_t off = (size_t)(b * 64 + (idx >> 7)) * HS + sh + (idx & 127);
        float e = __half2float(Eh[off]) + __half2float(El[off]);
        float o = __half2float(Oh[off]) + __half2float(Ol[off]);
        xs[idx] = 0.5f * (hi ? (e - o) : (e + o));
    }
    if (tid < 128) { b1s[tid] = fc1b[tid]; fc2s[tid] = fc2w[tid]; }
    __syncthreads();

    int tm = tid >> 4, tn = tid & 15;
    float acc[8][8];
    #pragma unroll
    for (int i = 0; i < 8; i++)
        #pragma unroll
        for (int j = 0; j < 8; j++) acc[i][j] = 0.0f;
    for (int i = 0; i < 64; i++) {
        float av[8], bv[8];
        #pragma unroll
        for (int ii = 0; ii < 8; ii++) av[ii] = xs[i * 128 + tm * 8 + ii];
        #pragma unroll
        for (int jj = 0; jj < 8; jj++) bv[jj] = fc1s[i * 128 + tn * 8 + jj];
        #pragma unroll
        for (int ii = 0; ii < 8; ii++)
            #pragma unroll
            for (int jj = 0; jj < 8; jj++) acc[ii][jj] += av[ii] * bv[jj];
    }
    float part[8];
    #pragma unroll
    for (int ii = 0; ii < 8; ii++) {
        float p = 0.0f;
        #pragma unroll
        for (int jj = 0; jj < 8; jj++) {
            float h = gelu_f(acc[ii][jj] + b1s[tn * 8 + jj]);
            p += h * fc2s[tn * 8 + jj];
        }
        part[ii] = p;
    }
    __syncthreads();
    float* red = xs;
    #pragma unroll
    for (int ii = 0; ii < 8; ii++) red[(tm * 8 + ii) * 16 + tn] = part[ii];
    __syncthreads();
    if (tid < 128) {
        float ssum = fc2b[0];
        #pragma unroll
        for (int t = 0; t < 16; t++) ssum += red[tid * 16 + t];
        out[(size_t)b * S + s0 + tid] = ssum;
    }
}

// ---------------------------------------------------------------------------
extern "C" void kernel_launch(void* const* d_in, const int* in_sizes, int n_in,
                              void* d_out, int out_size) {
    const float* u    = (const float*)d_in[0];
    const float* fc0w = (const float*)d_in[1];
    const float* fc0b = (const float*)d_in[2];
    const float* swr  = (const float*)d_in[3];
    const float* swi  = (const float*)d_in[4];
    const float* pww  = (const float*)d_in[5];
    const float* pwb  = (const float*)d_in[6];
    const float* fc1w = (const float*)d_in[7];
    const float* fc1b = (const float*)d_in[8];
    const float* fc2w = (const float*)d_in[9];
    const float* fc2b = (const float*)d_in[10];
    float* out = (float*)d_out;

    cudaFuncSetAttribute(mixk,   cudaFuncAttributeMaxDynamicSharedMemorySize, 67584);
    cudaFuncSetAttribute(headk,  cudaFuncAttributeMaxDynamicSharedMemorySize, 66560);
    cudaFuncSetAttribute(tc_fwd, cudaFuncAttributeMaxDynamicSharedMemorySize, 49152);
    cudaFuncSetAttribute(tc_inv, cudaFuncAttributeMaxDynamicSharedMemorySize, 73728);

    __half *pE0h, *pE0l, *pO0h, *pO0l, *pE1h, *pE1l, *pO1h, *pO1l;
    cudaGetSymbolAddress((void**)&pE0h, d_E0h);
    cudaGetSymbolAddress((void**)&pE0l, d_E0l);
    cudaGetSymbolAddress((void**)&pO0h, d_O0h);
    cudaGetSymbolAddress((void**)&pO0l, d_O0l);
    cudaGetSymbolAddress((void**)&pE1h, d_E1h);
    cudaGetSymbolAddress((void**)&pE1l, d_E1l);
    cudaGetSymbolAddress((void**)&pO1h, d_O1h);
    cudaGetSymbolAddress((void**)&pO1l, d_O1l);

    gen_table<<<32, 256>>>();
    gen_basis<<<4096, 256>>>();
    wtrans<<<dim3(8, 512, 2), dim3(32, 32)>>>(swr, swi);
    lift_fold<<<32768, 256>>>(u, fc0w, fc0b, pE0h, pE0l, pO0h, pO0l);

    __half *Eih = pE0h, *Eil = pE0l, *Oih = pO0h, *Oil = pO0l;
    __half *Eoh = pE1h, *Eol = pE1l, *Ooh = pO1h, *Ool = pO1l;
    for (int l = 0; l < 4; l++) {
        tc_fwd<<<dim3(2, 32, 2), 256, 49152>>>(Eih, Eil, Oih, Oil);
        mixk<<<256, 256, 67584>>>(l);
        pwpack<<<1024, 256>>>(pww + l * W * W);
        tc_inv<<<dim3(32, 64), 256, 73728>>>(Eih, Eil, Oih, Oil,
                                             Eoh, Eol, Ooh, Ool,
                                             pwb + l * W, (l < 3) ? 1 : 0);
        __half* t;
        t = Eih; Eih = Eoh; Eoh = t;
        t = Eil; Eil = Eol; Eol = t;
        t = Oih; Oih = Ooh; Ooh = t;
        t = Oil; Oil = Ool; Ool = t;
    }
    headk<<<dim3(64, 64), 256, 66560>>>(Eih, Eil, Oih, Oil,
                                        fc1w, fc1b, fc2w, fc2b, out);
}